// round 14
// baseline (speedup 1.0000x reference)
#include <cuda_runtime.h>
#include <math_constants.h>

#define N_PTS 65536
#define KNNK 54
#define GRIDD 16
#define NCELL 4096
#define CELLH 0.0625f
#define MBLK 256     // mlpK: 256 blocks x 256 threads

#define TWO_PI_F 6.28318530717958647692f
#define PI_F     3.14159265358979323846f
#define SQRT3_F  1.73205080756887729353f

// ---------------- scratch (static device memory; no allocation) ----------------
__device__ float4 d_sorted[N_PTS];      // (x, y, z, psq) in grid-sorted order
__device__ int d_sid[N_PTS];            // original point id per sorted position
__device__ int d_cellStart[NCELL + 1];
__device__ int d_cellPtr[NCELL];
__device__ int d_cnt[NCELL];
__device__ unsigned long long d_key[N_PTS * KNNK];   // (mapped-d<<16)|orig_id, [sp][slot]
__device__ unsigned short d_idx16[N_PTS * KNNK];     // sorted neighbor orig-ids [sp][slot]
__device__ float d_h[N_PTS * KNNK * 10];             // [ch][sp]
__device__ float d_part[MBLK * 20];
__device__ float d_bn[20];

// canonical (+,+,+) octant: 27 cell offsets sorted by min box distance
__constant__ char4 c_ord[27] = {
    { 0, 0, 0, 0},
    { 1, 0, 0, 0}, { 0, 1, 0, 0}, { 0, 0, 1, 0},
    { 1, 1, 0, 0}, { 1, 0, 1, 0}, { 0, 1, 1, 0},
    { 1, 1, 1, 0},
    {-1, 0, 0, 0}, { 0,-1, 0, 0}, { 0, 0,-1, 0},
    {-1, 1, 0, 0}, {-1, 0, 1, 0}, { 1,-1, 0, 0},
    { 0,-1, 1, 0}, { 1, 0,-1, 0}, { 0, 1,-1, 0},
    {-1, 1, 1, 0}, { 1,-1, 1, 0}, { 1, 1,-1, 0},
    {-1,-1, 0, 0}, {-1, 0,-1, 0}, { 0,-1,-1, 0},
    {-1,-1, 1, 0}, {-1, 1,-1, 0}, { 1,-1,-1, 0},
    {-1,-1,-1, 0}
};

__device__ __forceinline__ int cellCoord(float v) {
    int c = (int)floorf(v * 16.0f);
    c = c < 0 ? 0 : c;
    return c > (GRIDD - 1) ? (GRIDD - 1) : c;
}

__device__ __forceinline__ float sumsq_rn(float x, float y, float z) {
    return __fadd_rn(__fadd_rn(__fmul_rn(x, x), __fmul_rn(y, y)), __fmul_rn(z, z));
}

__device__ __forceinline__ float dot3_fma(float ax, float ay, float az,
                                          float bx, float by, float bz) {
    return __fmaf_rn(az, bz, __fmaf_rn(ay, by, __fmul_rn(ax, bx)));
}

__device__ __forceinline__ unsigned mapf(float d) {
    unsigned u = __float_as_uint(d);
    return (u & 0x80000000u) ? ~u : (u | 0x80000000u);
}
__device__ __forceinline__ float unmapf(unsigned m) {
    unsigned u = (m & 0x80000000u) ? (m & 0x7FFFFFFFu) : ~m;
    return __uint_as_float(u);
}

// ---------------- grid build ----------------
__global__ void countK(const float* __restrict__ c) {
    int i = blockIdx.x * blockDim.x + threadIdx.x;
    if (i >= N_PTS) return;
    int cx = cellCoord(c[3 * i]);
    int cy = cellCoord(c[3 * i + 1]);
    int cz = cellCoord(c[3 * i + 2]);
    atomicAdd(&d_cnt[(cz * GRIDD + cy) * GRIDD + cx], 1);
}

__global__ __launch_bounds__(1024) void scanK() {
    __shared__ int s[1024];
    int t = threadIdx.x;
    int v0 = d_cnt[4 * t], v1 = d_cnt[4 * t + 1], v2 = d_cnt[4 * t + 2], v3 = d_cnt[4 * t + 3];
    int tot = v0 + v1 + v2 + v3;
    s[t] = tot;
    __syncthreads();
    for (int off = 1; off < 1024; off <<= 1) {
        int x = (t >= off) ? s[t - off] : 0;
        __syncthreads();
        s[t] += x;
        __syncthreads();
    }
    int excl = s[t] - tot;
    d_cellStart[4 * t] = excl;
    d_cellStart[4 * t + 1] = excl + v0;
    d_cellStart[4 * t + 2] = excl + v0 + v1;
    d_cellStart[4 * t + 3] = excl + v0 + v1 + v2;
    d_cellPtr[4 * t] = excl;
    d_cellPtr[4 * t + 1] = excl + v0;
    d_cellPtr[4 * t + 2] = excl + v0 + v1;
    d_cellPtr[4 * t + 3] = excl + v0 + v1 + v2;
    if (t == 1023) d_cellStart[NCELL] = s[1023];
}

__global__ void scatterK(const float* __restrict__ c) {
    int i = blockIdx.x * blockDim.x + threadIdx.x;
    if (i >= N_PTS) return;
    float x = c[3 * i], y = c[3 * i + 1], z = c[3 * i + 2];
    int cid = (cellCoord(z) * GRIDD + cellCoord(y)) * GRIDD + cellCoord(x);
    int pos = atomicAdd(&d_cellPtr[cid], 1);
    d_sorted[pos] = make_float4(x, y, z, sumsq_rn(x, y, z));
    d_sid[pos] = i;
}

// ---------------- KNN: u64 smem top-54, tracked worst group, 8-wide MLP batching ----------------
__global__ __launch_bounds__(64) void knnK() {
    __shared__ unsigned long long sKV[KNNK * 64];
    int tid = threadIdx.x;
    int t = blockIdx.x * 64 + tid;      // sorted position
    float4 q = d_sorted[t];
    float qx = q.x, qy = q.y, qz = q.z;
    float qsq = q.w;
    int cx = cellCoord(qx), cy = cellCoord(qy), cz = cellCoord(qz);

    int count = 0;
    unsigned long long gm[9];
    unsigned long long wkey = 0xFFFFFFFFFFFFFFFFull;
    int wg = 0;
    float worst_d = CUDART_INF_F;

    auto accept = [&](float d, int p) {
        unsigned pi = (unsigned)d_sid[p];     // ORIGINAL id: tie-break semantics
        unsigned long long nk = ((unsigned long long)mapf(d) << 16) | pi;
        if (count < KNNK) {
            sKV[count * 64 + tid] = nk;
            count++;
            if (count == KNNK) {
                unsigned long long w = 0ULL; int wgl = 0;
#pragma unroll
                for (int g = 0; g < 9; g++) {
                    unsigned long long gv = 0ULL;
#pragma unroll
                    for (int j = 0; j < 6; j++) {
                        unsigned long long v = sKV[(g * 6 + j) * 64 + tid];
                        if (v > gv) gv = v;
                    }
                    gm[g] = gv;
                    if (gv > w) { w = gv; wgl = g; }
                }
                wkey = w; wg = wgl;
                worst_d = unmapf((unsigned)(w >> 16));
            }
        } else if (nk < wkey) {
            int base = wg * 6;
            unsigned long long m1 = 0ULL, m2 = 0ULL;
            int ms = base;
#pragma unroll
            for (int j = 0; j < 6; j++) {
                unsigned long long v = sKV[(base + j) * 64 + tid];
                if (v > m1) { m2 = m1; m1 = v; ms = base + j; }
                else if (v > m2) m2 = v;
            }
            sKV[ms * 64 + tid] = nk;
            gm[wg] = nk > m2 ? nk : m2;
            unsigned long long w = gm[0]; int wgl = 0;
#pragma unroll
            for (int g = 1; g < 9; g++) if (gm[g] > w) { w = gm[g]; wgl = g; }
            wkey = w; wg = wgl;
            worst_d = unmapf((unsigned)(w >> 16));
        }
    };

    auto processCell = [&](int cid) {
        int s = d_cellStart[cid], e = d_cellStart[cid + 1];
        int p = s;
        // 8-wide batched main loop: 8 independent gathers in flight
        for (; p + 8 <= e; p += 8) {
            float4 a0 = d_sorted[p];
            float4 a1 = d_sorted[p + 1];
            float4 a2 = d_sorted[p + 2];
            float4 a3 = d_sorted[p + 3];
            float4 a4 = d_sorted[p + 4];
            float4 a5 = d_sorted[p + 5];
            float4 a6 = d_sorted[p + 6];
            float4 a7 = d_sorted[p + 7];
            float d0 = __fsub_rn(__fadd_rn(qsq, a0.w),
                                 __fmul_rn(2.0f, dot3_fma(qx, qy, qz, a0.x, a0.y, a0.z)));
            float d1 = __fsub_rn(__fadd_rn(qsq, a1.w),
                                 __fmul_rn(2.0f, dot3_fma(qx, qy, qz, a1.x, a1.y, a1.z)));
            float d2 = __fsub_rn(__fadd_rn(qsq, a2.w),
                                 __fmul_rn(2.0f, dot3_fma(qx, qy, qz, a2.x, a2.y, a2.z)));
            float d3 = __fsub_rn(__fadd_rn(qsq, a3.w),
                                 __fmul_rn(2.0f, dot3_fma(qx, qy, qz, a3.x, a3.y, a3.z)));
            float d4 = __fsub_rn(__fadd_rn(qsq, a4.w),
                                 __fmul_rn(2.0f, dot3_fma(qx, qy, qz, a4.x, a4.y, a4.z)));
            float d5 = __fsub_rn(__fadd_rn(qsq, a5.w),
                                 __fmul_rn(2.0f, dot3_fma(qx, qy, qz, a5.x, a5.y, a5.z)));
            float d6 = __fsub_rn(__fadd_rn(qsq, a6.w),
                                 __fmul_rn(2.0f, dot3_fma(qx, qy, qz, a6.x, a6.y, a6.z)));
            float d7 = __fsub_rn(__fadd_rn(qsq, a7.w),
                                 __fmul_rn(2.0f, dot3_fma(qx, qy, qz, a7.x, a7.y, a7.z)));
            // sequential exact checks (worst_d may tighten between them)
            if (d0 <= worst_d) accept(d0, p);
            if (d1 <= worst_d) accept(d1, p + 1);
            if (d2 <= worst_d) accept(d2, p + 2);
            if (d3 <= worst_d) accept(d3, p + 3);
            if (d4 <= worst_d) accept(d4, p + 4);
            if (d5 <= worst_d) accept(d5, p + 5);
            if (d6 <= worst_d) accept(d6, p + 6);
            if (d7 <= worst_d) accept(d7, p + 7);
        }
        // 4-wide mid loop
        for (; p + 4 <= e; p += 4) {
            float4 a0 = d_sorted[p];
            float4 a1 = d_sorted[p + 1];
            float4 a2 = d_sorted[p + 2];
            float4 a3 = d_sorted[p + 3];
            float d0 = __fsub_rn(__fadd_rn(qsq, a0.w),
                                 __fmul_rn(2.0f, dot3_fma(qx, qy, qz, a0.x, a0.y, a0.z)));
            float d1 = __fsub_rn(__fadd_rn(qsq, a1.w),
                                 __fmul_rn(2.0f, dot3_fma(qx, qy, qz, a1.x, a1.y, a1.z)));
            float d2 = __fsub_rn(__fadd_rn(qsq, a2.w),
                                 __fmul_rn(2.0f, dot3_fma(qx, qy, qz, a2.x, a2.y, a2.z)));
            float d3 = __fsub_rn(__fadd_rn(qsq, a3.w),
                                 __fmul_rn(2.0f, dot3_fma(qx, qy, qz, a3.x, a3.y, a3.z)));
            if (d0 <= worst_d) accept(d0, p);
            if (d1 <= worst_d) accept(d1, p + 1);
            if (d2 <= worst_d) accept(d2, p + 2);
            if (d3 <= worst_d) accept(d3, p + 3);
        }
        for (; p < e; p++) {
            float4 a = d_sorted[p];
            float d = __fsub_rn(__fadd_rn(qsq, a.w),
                                __fmul_rn(2.0f, dot3_fma(qx, qy, qz, a.x, a.y, a.z)));
            if (d <= worst_d) accept(d, p);
        }
    };

    int sx = (qx > ((float)cx + 0.5f) * CELLH) ? 1 : -1;
    int sy = (qy > ((float)cy + 0.5f) * CELLH) ? 1 : -1;
    int sz = (qz > ((float)cz + 0.5f) * CELLH) ? 1 : -1;

#pragma unroll 1
    for (int o = 0; o < 27; o++) {
        char4 c = c_ord[o];
        int x = cx + sx * (int)c.x;
        int y = cy + sy * (int)c.y;
        int z = cz + sz * (int)c.z;
        if (((unsigned)x | (unsigned)y | (unsigned)z) > 15u) continue;
        float dxx = fmaxf(0.0f, fmaxf((float)x * CELLH - qx, qx - ((float)x * CELLH + CELLH)));
        float dyy = fmaxf(0.0f, fmaxf((float)y * CELLH - qy, qy - ((float)y * CELLH + CELLH)));
        float dzz = fmaxf(0.0f, fmaxf((float)z * CELLH - qz, qz - ((float)z * CELLH + CELLH)));
        if (dxx * dxx + dyy * dyy + dzz * dzz > worst_d + 4e-6f) continue;
        processCell((z * GRIDD + y) * GRIDD + x);
    }

    {
        float g = CUDART_INF_F;
        if (cx - 1 > 0)         g = fminf(g, qx - (float)(cx - 1) * CELLH);
        if (cx + 1 < GRIDD - 1) g = fminf(g, (float)(cx + 2) * CELLH - qx);
        if (cy - 1 > 0)         g = fminf(g, qy - (float)(cy - 1) * CELLH);
        if (cy + 1 < GRIDD - 1) g = fminf(g, (float)(cy + 2) * CELLH - qy);
        if (cz - 1 > 0)         g = fminf(g, qz - (float)(cz - 1) * CELLH);
        if (cz + 1 < GRIDD - 1) g = fminf(g, (float)(cz + 2) * CELLH - qz);
        if (worst_d + 4e-6f < g * g) goto done;
    }

    {
        int maxm = cx; if (GRIDD - 1 - cx > maxm) maxm = GRIDD - 1 - cx;
        if (cy > maxm) maxm = cy; if (GRIDD - 1 - cy > maxm) maxm = GRIDD - 1 - cy;
        if (cz > maxm) maxm = cz; if (GRIDD - 1 - cz > maxm) maxm = GRIDD - 1 - cz;

        for (int m = 2; m <= maxm; m++) {
            int zlo = cz - m < 0 ? 0 : cz - m;
            int zhi = cz + m > GRIDD - 1 ? GRIDD - 1 : cz + m;
            for (int z = zlo; z <= zhi; z++) {
                int adz = z - cz; adz = adz < 0 ? -adz : adz;
                float lo = (float)z * CELLH, hi = lo + CELLH;
                float dz = fmaxf(0.0f, fmaxf(lo - qz, qz - hi));
                float dz2 = dz * dz;
                int ylo = cy - m < 0 ? 0 : cy - m;
                int yhi = cy + m > GRIDD - 1 ? GRIDD - 1 : cy + m;
                for (int y = ylo; y <= yhi; y++) {
                    int ady = y - cy; ady = ady < 0 ? -ady : ady;
                    float lyo = (float)y * CELLH, lyh = lyo + CELLH;
                    float dy = fmaxf(0.0f, fmaxf(lyo - qy, qy - lyh));
                    float dyz2 = dz2 + dy * dy;
                    if (dyz2 > worst_d + 4e-6f) continue;
                    int xlo = cx - m < 0 ? 0 : cx - m;
                    int xhi = cx + m > GRIDD - 1 ? GRIDD - 1 : cx + m;
                    for (int x = xlo; x <= xhi; x++) {
                        int adx = x - cx; adx = adx < 0 ? -adx : adx;
                        int cheb = adx > ady ? adx : ady;
                        if (adz > cheb) cheb = adz;
                        if (cheb != m) continue;
                        float lxo = (float)x * CELLH, lxh = lxo + CELLH;
                        float dx = fmaxf(0.0f, fmaxf(lxo - qx, qx - lxh));
                        if (dyz2 + dx * dx > worst_d + 4e-6f) continue;
                        processCell((z * GRIDD + y) * GRIDD + x);
                    }
                }
            }
            float g = CUDART_INF_F;
            if (cx - m > 0)         g = fminf(g, qx - (float)(cx - m) * CELLH);
            if (cx + m < GRIDD - 1) g = fminf(g, (float)(cx + m + 1) * CELLH - qx);
            if (cy - m > 0)         g = fminf(g, qy - (float)(cy - m) * CELLH);
            if (cy + m < GRIDD - 1) g = fminf(g, (float)(cy + m + 1) * CELLH - qy);
            if (cz - m > 0)         g = fminf(g, qz - (float)(cz - m) * CELLH);
            if (cz + m < GRIDD - 1) g = fminf(g, (float)(cz + m + 1) * CELLH - qz);
            if (worst_d + 4e-6f < g * g) break;
        }
    }

done:
#pragma unroll
    for (int j = 0; j < KNNK; j++) d_key[(size_t)t * KNNK + j] = sKV[j * 64 + tid];
}

// ---------------- sortK: warp-per-point register bitonic sorts (grid-sorted order) ----------------
__device__ __forceinline__ void ceA(unsigned long long& h, unsigned& l, int dl, bool keep_min) {
    unsigned long long oh = __shfl_xor_sync(0xFFFFFFFFu, h, dl);
    unsigned ol = __shfl_xor_sync(0xFFFFFFFFu, l, dl);
    bool mine_le = (h < oh) || (h == oh && l <= ol);
    if (mine_le != keep_min) { h = oh; l = ol; }
}
__device__ __forceinline__ void ceB(unsigned long long& h, int dl, bool keep_min) {
    unsigned long long oh = __shfl_xor_sync(0xFFFFFFFFu, h, dl);
    bool mine_le = (h <= oh);
    if (mine_le != keep_min) h = oh;
}

__global__ __launch_bounds__(256) void sortK(const float* __restrict__ cen) {
    int tid = threadIdx.x;
    int lane = tid & 31;
    int wrp = tid >> 5;
    int sp = blockIdx.x * 8 + wrp;

    float4 q = d_sorted[sp];
    float qx = q.x, qy = q.y, qz = q.z;

    const int e0 = 2 * lane, e1 = 2 * lane + 1;
    unsigned long long h0 = ~0ULL, h1 = ~0ULL;
    unsigned l0 = 0xFFFFFFFFu, l1 = 0xFFFFFFFFu;

#pragma unroll
    for (int s = 0; s < 2; s++) {
        int e = s ? e1 : e0;
        if (e < KNNK) {
            unsigned long long k = d_key[(size_t)sp * KNNK + e];
            unsigned id = (unsigned)(k & 0xFFFFull);
            unsigned d32 = (unsigned)(k >> 16);
            float x = __fsub_rn(cen[3 * id], qx);
            float y = __fsub_rn(cen[3 * id + 1], qy);
            float z = __fsub_rn(cen[3 * id + 2], qz);
            float rx = __fmaf_rn(z, -0.5f,    __fmaf_rn(y, 0.7071f, __fmul_rn(x,  0.5f)));
            float ry = __fmaf_rn(z,  0.5f,    __fmaf_rn(y, 0.7071f, __fmul_rn(x, -0.5f)));
            float rz = __fmaf_rn(z,  0.7071f, __fmul_rn(x, 0.7071f));
            float rho = __fsqrt_rn(sumsq_rn(rx, ry, rz));
            unsigned long long h = ((unsigned long long)mapf(rho) << 32) | (unsigned long long)d32;
            if (s) { h1 = h; l1 = id; } else { h0 = h; l0 = id; }
        }
    }

#pragma unroll
    for (int k = 2; k <= 64; k <<= 1) {
        bool asc = ((lane & (k >> 1)) == 0);
#pragma unroll
        for (int j = k >> 1; j >= 2; j >>= 1) {
            int dl = j >> 1;
            bool km = (((lane & dl) == 0) == asc);
            ceA(h0, l0, dl, km);
            ceA(h1, l1, dl, km);
        }
        bool r0_le = (h0 < h1) || (h0 == h1 && l0 <= l1);
        if (r0_le != asc) {
            unsigned long long th = h0; h0 = h1; h1 = th;
            unsigned tl = l0; l0 = l1; l1 = tl;
        }
    }

    unsigned long long b0 = ~0ULL, b1 = ~0ULL;
#pragma unroll
    for (int s = 0; s < 2; s++) {
        int e = s ? e1 : e0;
        unsigned id = (s ? l1 : l0) & 0xFFFFu;
        if (e < KNNK) {
            float x = __fsub_rn(cen[3 * id], qx);
            float y = __fsub_rn(cen[3 * id + 1], qy);
            float z = __fsub_rn(cen[3 * id + 2], qz);
            float rx = __fmaf_rn(z, -0.5f, __fmaf_rn(y, 0.7071f, __fmul_rn(x,  0.5f)));
            float ry = __fmaf_rn(z,  0.5f, __fmaf_rn(y, 0.7071f, __fmul_rn(x, -0.5f)));
            float phi = __fadd_rn(__fdiv_rn(atan2f(ry, rx), TWO_PI_F), 0.5f);
            unsigned long long seg = (e < 9) ? 0ULL : (e < 27) ? 1ULL : 2ULL;
            unsigned long long b = (seg << 54)
                                 | ((unsigned long long)mapf(phi) << 22)
                                 | ((unsigned long long)e << 16)
                                 | (unsigned long long)id;
            if (s) b1 = b; else b0 = b;
        }
    }

#pragma unroll
    for (int k = 2; k <= 64; k <<= 1) {
        bool asc = ((lane & (k >> 1)) == 0);
#pragma unroll
        for (int j = k >> 1; j >= 2; j >>= 1) {
            int dl = j >> 1;
            bool km = (((lane & dl) == 0) == asc);
            ceB(b0, dl, km);
            ceB(b1, dl, km);
        }
        if ((b0 <= b1) != asc) {
            unsigned long long tb = b0; b0 = b1; b1 = tb;
        }
    }

    if (e0 < KNNK) d_idx16[(size_t)sp * KNNK + e0] = (unsigned short)(b0 & 0xFFFFull);
    if (e1 < KNNK) d_idx16[(size_t)sp * KNNK + e1] = (unsigned short)(b1 & 0xFFFFull);
}

// ---------------- mlpK: SINGLE-PASS triangles + layer1 + BN partials, rare bad-fixup ----------------
__global__ __launch_bounds__(256) void mlpK(const float* __restrict__ cen,
                                            const float* __restrict__ W1,
                                            const float* __restrict__ b1) {
    __shared__ float sW1[100], sb1[10];
    __shared__ float sWS[8][20];
    int tid = threadIdx.x;
    if (tid < 100) sW1[tid] = W1[tid];
    if (tid < 10) sb1[tid] = b1[tid];
    __syncthreads();

    int sp = blockIdx.x * 256 + tid;
    float4 q = d_sorted[sp];
    float qx = q.x, qy = q.y, qz = q.z;

    auto idxAt = [&](int i) -> int { return (int)d_idx16[(size_t)sp * KNNK + i]; };
    auto nextT = [](int t) -> int {
        int base, len;
        if (t < 9) { base = 0; len = 9; }
        else if (t < 27) { base = 9; len = 18; }
        else { base = 27; len = 27; }
        int loc = t - base + 1;
        return base + (loc == len ? 0 : loc);
    };

    float pm = 1.0f;
    unsigned long long badm = 0ULL;
    int first = -1;

    float s0[10], s1[10];
#pragma unroll
    for (int c = 0; c < 10; c++) { s0[c] = 0.0f; s1[c] = 0.0f; }

    for (int t = 0; t < 54; t++) {
        int na = idxAt(t), nb = idxAt(nextT(t));
        float e1x = __fsub_rn(cen[3 * na], qx);
        float e1y = __fsub_rn(cen[3 * na + 1], qy);
        float e1z = __fsub_rn(cen[3 * na + 2], qz);
        float e2x = __fsub_rn(cen[3 * nb], qx);
        float e2y = __fsub_rn(cen[3 * nb + 1], qy);
        float e2z = __fsub_rn(cen[3 * nb + 2], qz);
        float nx = __fsub_rn(__fmul_rn(e1y, e2z), __fmul_rn(e1z, e2y));
        float ny = __fsub_rn(__fmul_rn(e1z, e2x), __fmul_rn(e1x, e2z));
        float nz = __fsub_rn(__fmul_rn(e1x, e2y), __fmul_rn(e1y, e2x));
        float nl = __fsqrt_rn(sumsq_rn(nx, ny, nz));
        bool bad = (nl == 0.0f);
        float ux, uy, uz;
        if (bad) { ux = 0.0f; uy = 0.0f; uz = 0.0f; }
        else {
            ux = __fdiv_rn(nx, nl); uy = __fdiv_rn(ny, nl); uz = __fdiv_rn(nz, nl);
        }
        if (t == 0) pm = (ux > 0.0f) ? 1.0f : -1.0f;
        ux = __fmul_rn(ux, pm); uy = __fmul_rn(uy, pm); uz = __fmul_rn(uz, pm);
        float ccx = __fdiv_rn(__fadd_rn(e1x, e2x), 3.0f);
        float ccy = __fdiv_rn(__fadd_rn(e1y, e2y), 3.0f);
        float ccz = __fdiv_rn(__fadd_rn(e1z, e2z), 3.0f);
        float pos = __fdiv_rn(
            __fadd_rn(__fadd_rn(__fmul_rn(ux, ccx), __fmul_rn(uy, ccy)), __fmul_rn(uz, ccz)),
            SQRT3_F);

        float rho = __fsqrt_rn(sumsq_rn(ccx, ccy, ccz));
        float phi = __fadd_rn(__fdiv_rn(atan2f(ccy, ccx), TWO_PI_F), 0.5f);
        float theta;
        if (rho == 0.0f) theta = 0.0f;
        else {
            float r = __fdiv_rn(ccz, rho);
            r = fminf(1.0f, fmaxf(-1.0f, r));
            theta = __fdiv_rn(acosf(r), PI_F);
        }
        float f[10];
        f[0] = rho; f[1] = theta; f[2] = phi;
        f[3] = ux; f[4] = uy; f[5] = uz;
        f[6] = pos;
        f[7] = ccx; f[8] = ccy; f[9] = ccz;

        int chBase = t * 10;
#pragma unroll
        for (int c = 0; c < 10; c++) {
            float acc = 0.0f;
#pragma unroll
            for (int k = 0; k < 10; k++) acc += f[k] * sW1[c * 10 + k];
            float h = acc + sb1[c];
            d_h[(size_t)(chBase + c) * N_PTS + sp] = h;
            s0[c] += h;
            s1[c] += h * h;
        }

        if (bad) badm |= (1ULL << t);
        else if (first < 0) first = t;
    }

    if (badm != 0ULL) {
        if (first < 0) first = 0;
        float fux, fuy, fuz, fcx, fcy, fcz, fpos;
        {
            int na = idxAt(first), nb = idxAt(nextT(first));
            float e1x = __fsub_rn(cen[3 * na], qx);
            float e1y = __fsub_rn(cen[3 * na + 1], qy);
            float e1z = __fsub_rn(cen[3 * na + 2], qz);
            float e2x = __fsub_rn(cen[3 * nb], qx);
            float e2y = __fsub_rn(cen[3 * nb + 1], qy);
            float e2z = __fsub_rn(cen[3 * nb + 2], qz);
            float nx = __fsub_rn(__fmul_rn(e1y, e2z), __fmul_rn(e1z, e2y));
            float ny = __fsub_rn(__fmul_rn(e1z, e2x), __fmul_rn(e1x, e2z));
            float nz = __fsub_rn(__fmul_rn(e1x, e2y), __fmul_rn(e1y, e2x));
            float nl = __fsqrt_rn(sumsq_rn(nx, ny, nz));
            bool bad = (nl == 0.0f);
            if (bad) { fux = 0.0f; fuy = 0.0f; fuz = 0.0f; }
            else {
                fux = __fdiv_rn(nx, nl); fuy = __fdiv_rn(ny, nl); fuz = __fdiv_rn(nz, nl);
            }
            fux = __fmul_rn(fux, pm); fuy = __fmul_rn(fuy, pm); fuz = __fmul_rn(fuz, pm);
            fcx = __fdiv_rn(__fadd_rn(e1x, e2x), 3.0f);
            fcy = __fdiv_rn(__fadd_rn(e1y, e2y), 3.0f);
            fcz = __fdiv_rn(__fadd_rn(e1z, e2z), 3.0f);
            fpos = __fdiv_rn(
                __fadd_rn(__fadd_rn(__fmul_rn(fux, fcx), __fmul_rn(fuy, fcy)), __fmul_rn(fuz, fcz)),
                SQRT3_F);
        }
        unsigned long long m = badm;
        while (m) {
            int t = __ffsll((long long)m) - 1;
            m &= m - 1ULL;
            int na = idxAt(t), nb = idxAt(nextT(t));
            float e1x = __fsub_rn(cen[3 * na], qx);
            float e1y = __fsub_rn(cen[3 * na + 1], qy);
            float e1z = __fsub_rn(cen[3 * na + 2], qz);
            float e2x = __fsub_rn(cen[3 * nb], qx);
            float e2y = __fsub_rn(cen[3 * nb + 1], qy);
            float e2z = __fsub_rn(cen[3 * nb + 2], qz);
            float ccx = __fdiv_rn(__fadd_rn(e1x, e2x), 3.0f);
            float ccy = __fdiv_rn(__fadd_rn(e1y, e2y), 3.0f);
            float ccz = __fdiv_rn(__fadd_rn(e1z, e2z), 3.0f);
            float rho = __fsqrt_rn(sumsq_rn(ccx, ccy, ccz));
            float phi = __fadd_rn(__fdiv_rn(atan2f(ccy, ccx), TWO_PI_F), 0.5f);
            float theta;
            if (rho == 0.0f) theta = 0.0f;
            else {
                float r = __fdiv_rn(ccz, rho);
                r = fminf(1.0f, fmaxf(-1.0f, r));
                theta = __fdiv_rn(acosf(r), PI_F);
            }
            float f[10];
            f[0] = rho; f[1] = theta; f[2] = phi;
            f[3] = fux; f[4] = fuy; f[5] = fuz;
            f[6] = fpos;
            f[7] = fcx; f[8] = fcy; f[9] = fcz;

            int chBase = t * 10;
#pragma unroll
            for (int c = 0; c < 10; c++) {
                float acc = 0.0f;
#pragma unroll
                for (int k = 0; k < 10; k++) acc += f[k] * sW1[c * 10 + k];
                float hn = acc + sb1[c];
                size_t off = (size_t)(chBase + c) * N_PTS + sp;
                float ho = d_h[off];
                d_h[off] = hn;
                s0[c] = s0[c] - ho + hn;
                s1[c] = s1[c] - ho * ho + hn * hn;
            }
        }
    }

    int lane = tid & 31, wrp = tid >> 5;
#pragma unroll
    for (int v = 0; v < 20; v++) {
        float a = (v < 10) ? s0[v] : s1[v - 10];
#pragma unroll
        for (int off = 16; off > 0; off >>= 1) a += __shfl_down_sync(0xFFFFFFFFu, a, off);
        if (lane == 0) sWS[wrp][v] = a;
    }
    __syncthreads();
    if (tid < 20) {
        float a = 0.0f;
#pragma unroll
        for (int w = 0; w < 8; w++) a += sWS[w][tid];
        d_part[blockIdx.x * 20 + tid] = a;
    }
}

// ---------------- BN finalize ----------------
__global__ __launch_bounds__(640) void bnK(const float* __restrict__ gamma,
                                           const float* __restrict__ beta) {
    __shared__ float S[20];
    int tid = threadIdx.x;
    int w = tid / 32, l = tid % 32;
    float a = 0.0f;
    for (int k = l; k < MBLK; k += 32) a += d_part[k * 20 + w];
#pragma unroll
    for (int off = 16; off > 0; off >>= 1) a += __shfl_down_sync(0xFFFFFFFFu, a, off);
    if (l == 0) S[w] = a;
    __syncthreads();
    if (tid < 10) {
        const double M = (double)N_PTS * 54.0;
        double mu = (double)S[tid] / M;
        double var = (double)S[tid + 10] / M - mu * mu;
        if (var < 0.0) var = 0.0;
        float sc = gamma[tid] * rsqrtf((float)var + 1e-5f);
        d_bn[tid] = sc;
        d_bn[10 + tid] = beta[tid] - (float)mu * sc;
    }
}

// ---------------- BN affine + relu + layer2 + sum over 54 (sorted order, scatter out) ----------------
__global__ __launch_bounds__(256) void outK(const float* __restrict__ W2,
                                            const float* __restrict__ b2,
                                            float* __restrict__ out) {
    __shared__ float sa[10], sb[10], sW2[100], sb2[10];
    int tid = threadIdx.x;
    if (tid < 10) { sa[tid] = d_bn[tid]; sb[tid] = d_bn[10 + tid]; sb2[tid] = b2[tid]; }
    if (tid < 100) sW2[tid] = W2[tid];
    __syncthreads();

    int sp = blockIdx.x * blockDim.x + tid;
    float acc[10];
#pragma unroll
    for (int c = 0; c < 10; c++) acc[c] = 0.0f;
    for (int t = 0; t < 54; t++) {
#pragma unroll
        for (int c = 0; c < 10; c++) {
            float v = d_h[(size_t)(t * 10 + c) * N_PTS + sp] * sa[c] + sb[c];
            v = fmaxf(v, 0.0f);
            acc[c] += v;
        }
    }
    int p = d_sid[sp];
#pragma unroll
    for (int c = 0; c < 10; c++) {
        float o = 54.0f * sb2[c];
#pragma unroll
        for (int j = 0; j < 10; j++) o += acc[j] * sW2[c * 10 + j];
        out[p * 10 + c] = o;
    }
}

// ---------------- launch ----------------
extern "C" void kernel_launch(void* const* d_in, const int* in_sizes, int n_in,
                              void* d_out, int out_size) {
    const float* center = (const float*)d_in[0];
    const float* W1 = (const float*)d_in[2];
    const float* b1 = (const float*)d_in[3];
    const float* gamma = (const float*)d_in[4];
    const float* beta = (const float*)d_in[5];
    const float* W2 = (const float*)d_in[6];
    const float* b2 = (const float*)d_in[7];
    float* out = (float*)d_out;

    void* cntPtr = nullptr;
    cudaGetSymbolAddress(&cntPtr, d_cnt);
    cudaMemsetAsync(cntPtr, 0, NCELL * sizeof(int), 0);

    countK<<<256, 256>>>(center);
    scanK<<<1, 1024>>>();
    scatterK<<<256, 256>>>(center);
    knnK<<<1024, 64>>>();
    sortK<<<8192, 256>>>(center);
    mlpK<<<MBLK, 256>>>(center, W1, b1);
    bnK<<<1, 640>>>(gamma, beta);
    outK<<<256, 256>>>(W2, b2, out);
}

// round 15
// speedup vs baseline: 1.2855x; 1.2855x over previous
#include <cuda_runtime.h>
#include <math_constants.h>

#define N_PTS 65536
#define KNNK 54
#define GRIDD 16
#define NCELL 4096
#define CELLH 0.0625f
#define MBLK 512     // mlpK: 512 blocks x 256 threads (2 threads/point)

#define TWO_PI_F 6.28318530717958647692f
#define PI_F     3.14159265358979323846f
#define SQRT3_F  1.73205080756887729353f

// ---------------- scratch (static device memory; no allocation) ----------------
__device__ float4 d_sorted[N_PTS];      // (x, y, z, psq) in grid-sorted order
__device__ int d_sid[N_PTS];            // original point id per sorted position
__device__ int d_cellStart[NCELL + 1];
__device__ int d_cellPtr[NCELL];
__device__ int d_cnt[NCELL];
__device__ unsigned long long d_key[N_PTS * KNNK];   // (mapped-d<<16)|orig_id, [sp][slot]
__device__ unsigned short d_idx16[N_PTS * KNNK];     // sorted neighbor orig-ids [sp][slot]
__device__ float d_h[N_PTS * KNNK * 10];             // [ch][sp]
__device__ float d_part[MBLK * 20];
__device__ float d_bn[20];

// canonical (+,+,+) octant: 27 cell offsets sorted by min box distance
__constant__ char4 c_ord[27] = {
    { 0, 0, 0, 0},
    { 1, 0, 0, 0}, { 0, 1, 0, 0}, { 0, 0, 1, 0},
    { 1, 1, 0, 0}, { 1, 0, 1, 0}, { 0, 1, 1, 0},
    { 1, 1, 1, 0},
    {-1, 0, 0, 0}, { 0,-1, 0, 0}, { 0, 0,-1, 0},
    {-1, 1, 0, 0}, {-1, 0, 1, 0}, { 1,-1, 0, 0},
    { 0,-1, 1, 0}, { 1, 0,-1, 0}, { 0, 1,-1, 0},
    {-1, 1, 1, 0}, { 1,-1, 1, 0}, { 1, 1,-1, 0},
    {-1,-1, 0, 0}, {-1, 0,-1, 0}, { 0,-1,-1, 0},
    {-1,-1, 1, 0}, {-1, 1,-1, 0}, { 1,-1,-1, 0},
    {-1,-1,-1, 0}
};

__device__ __forceinline__ int cellCoord(float v) {
    int c = (int)floorf(v * 16.0f);
    c = c < 0 ? 0 : c;
    return c > (GRIDD - 1) ? (GRIDD - 1) : c;
}

__device__ __forceinline__ float sumsq_rn(float x, float y, float z) {
    return __fadd_rn(__fadd_rn(__fmul_rn(x, x), __fmul_rn(y, y)), __fmul_rn(z, z));
}

__device__ __forceinline__ float dot3_fma(float ax, float ay, float az,
                                          float bx, float by, float bz) {
    return __fmaf_rn(az, bz, __fmaf_rn(ay, by, __fmul_rn(ax, bx)));
}

__device__ __forceinline__ unsigned mapf(float d) {
    unsigned u = __float_as_uint(d);
    return (u & 0x80000000u) ? ~u : (u | 0x80000000u);
}
__device__ __forceinline__ float unmapf(unsigned m) {
    unsigned u = (m & 0x80000000u) ? (m & 0x7FFFFFFFu) : ~m;
    return __uint_as_float(u);
}

// ---------------- grid build ----------------
__global__ void countK(const float* __restrict__ c) {
    int i = blockIdx.x * blockDim.x + threadIdx.x;
    if (i >= N_PTS) return;
    int cx = cellCoord(c[3 * i]);
    int cy = cellCoord(c[3 * i + 1]);
    int cz = cellCoord(c[3 * i + 2]);
    atomicAdd(&d_cnt[(cz * GRIDD + cy) * GRIDD + cx], 1);
}

__global__ __launch_bounds__(1024) void scanK() {
    __shared__ int s[1024];
    int t = threadIdx.x;
    int v0 = d_cnt[4 * t], v1 = d_cnt[4 * t + 1], v2 = d_cnt[4 * t + 2], v3 = d_cnt[4 * t + 3];
    int tot = v0 + v1 + v2 + v3;
    s[t] = tot;
    __syncthreads();
    for (int off = 1; off < 1024; off <<= 1) {
        int x = (t >= off) ? s[t - off] : 0;
        __syncthreads();
        s[t] += x;
        __syncthreads();
    }
    int excl = s[t] - tot;
    d_cellStart[4 * t] = excl;
    d_cellStart[4 * t + 1] = excl + v0;
    d_cellStart[4 * t + 2] = excl + v0 + v1;
    d_cellStart[4 * t + 3] = excl + v0 + v1 + v2;
    d_cellPtr[4 * t] = excl;
    d_cellPtr[4 * t + 1] = excl + v0;
    d_cellPtr[4 * t + 2] = excl + v0 + v1;
    d_cellPtr[4 * t + 3] = excl + v0 + v1 + v2;
    if (t == 1023) d_cellStart[NCELL] = s[1023];
}

__global__ void scatterK(const float* __restrict__ c) {
    int i = blockIdx.x * blockDim.x + threadIdx.x;
    if (i >= N_PTS) return;
    float x = c[3 * i], y = c[3 * i + 1], z = c[3 * i + 2];
    int cid = (cellCoord(z) * GRIDD + cellCoord(y)) * GRIDD + cellCoord(x);
    int pos = atomicAdd(&d_cellPtr[cid], 1);
    d_sorted[pos] = make_float4(x, y, z, sumsq_rn(x, y, z));
    d_sid[pos] = i;
}

// ---------------- KNN: u64 smem top-54, tracked worst group, 4-wide MLP batching ----------------
__global__ __launch_bounds__(64) void knnK() {
    __shared__ unsigned long long sKV[KNNK * 64];
    int tid = threadIdx.x;
    int t = blockIdx.x * 64 + tid;      // sorted position
    float4 q = d_sorted[t];
    float qx = q.x, qy = q.y, qz = q.z;
    float qsq = q.w;
    int cx = cellCoord(qx), cy = cellCoord(qy), cz = cellCoord(qz);

    int count = 0;
    unsigned long long gm[9];
    unsigned long long wkey = 0xFFFFFFFFFFFFFFFFull;
    int wg = 0;
    float worst_d = CUDART_INF_F;

    auto accept = [&](float d, int p) {
        unsigned pi = (unsigned)d_sid[p];     // ORIGINAL id: tie-break semantics
        unsigned long long nk = ((unsigned long long)mapf(d) << 16) | pi;
        if (count < KNNK) {
            sKV[count * 64 + tid] = nk;
            count++;
            if (count == KNNK) {
                unsigned long long w = 0ULL; int wgl = 0;
#pragma unroll
                for (int g = 0; g < 9; g++) {
                    unsigned long long gv = 0ULL;
#pragma unroll
                    for (int j = 0; j < 6; j++) {
                        unsigned long long v = sKV[(g * 6 + j) * 64 + tid];
                        if (v > gv) gv = v;
                    }
                    gm[g] = gv;
                    if (gv > w) { w = gv; wgl = g; }
                }
                wkey = w; wg = wgl;
                worst_d = unmapf((unsigned)(w >> 16));
            }
        } else if (nk < wkey) {
            int base = wg * 6;
            unsigned long long m1 = 0ULL, m2 = 0ULL;
            int ms = base;
#pragma unroll
            for (int j = 0; j < 6; j++) {
                unsigned long long v = sKV[(base + j) * 64 + tid];
                if (v > m1) { m2 = m1; m1 = v; ms = base + j; }
                else if (v > m2) m2 = v;
            }
            sKV[ms * 64 + tid] = nk;
            gm[wg] = nk > m2 ? nk : m2;
            unsigned long long w = gm[0]; int wgl = 0;
#pragma unroll
            for (int g = 1; g < 9; g++) if (gm[g] > w) { w = gm[g]; wgl = g; }
            wkey = w; wg = wgl;
            worst_d = unmapf((unsigned)(w >> 16));
        }
    };

    auto processCell = [&](int cid) {
        int s = d_cellStart[cid], e = d_cellStart[cid + 1];
        int p = s;
        for (; p + 4 <= e; p += 4) {
            float4 a0 = d_sorted[p];
            float4 a1 = d_sorted[p + 1];
            float4 a2 = d_sorted[p + 2];
            float4 a3 = d_sorted[p + 3];
            float d0 = __fsub_rn(__fadd_rn(qsq, a0.w),
                                 __fmul_rn(2.0f, dot3_fma(qx, qy, qz, a0.x, a0.y, a0.z)));
            float d1 = __fsub_rn(__fadd_rn(qsq, a1.w),
                                 __fmul_rn(2.0f, dot3_fma(qx, qy, qz, a1.x, a1.y, a1.z)));
            float d2 = __fsub_rn(__fadd_rn(qsq, a2.w),
                                 __fmul_rn(2.0f, dot3_fma(qx, qy, qz, a2.x, a2.y, a2.z)));
            float d3 = __fsub_rn(__fadd_rn(qsq, a3.w),
                                 __fmul_rn(2.0f, dot3_fma(qx, qy, qz, a3.x, a3.y, a3.z)));
            if (d0 <= worst_d) accept(d0, p);
            if (d1 <= worst_d) accept(d1, p + 1);
            if (d2 <= worst_d) accept(d2, p + 2);
            if (d3 <= worst_d) accept(d3, p + 3);
        }
        for (; p < e; p++) {
            float4 a = d_sorted[p];
            float d = __fsub_rn(__fadd_rn(qsq, a.w),
                                __fmul_rn(2.0f, dot3_fma(qx, qy, qz, a.x, a.y, a.z)));
            if (d <= worst_d) accept(d, p);
        }
    };

    int sx = (qx > ((float)cx + 0.5f) * CELLH) ? 1 : -1;
    int sy = (qy > ((float)cy + 0.5f) * CELLH) ? 1 : -1;
    int sz = (qz > ((float)cz + 0.5f) * CELLH) ? 1 : -1;

#pragma unroll 1
    for (int o = 0; o < 27; o++) {
        char4 c = c_ord[o];
        int x = cx + sx * (int)c.x;
        int y = cy + sy * (int)c.y;
        int z = cz + sz * (int)c.z;
        if (((unsigned)x | (unsigned)y | (unsigned)z) > 15u) continue;
        float dxx = fmaxf(0.0f, fmaxf((float)x * CELLH - qx, qx - ((float)x * CELLH + CELLH)));
        float dyy = fmaxf(0.0f, fmaxf((float)y * CELLH - qy, qy - ((float)y * CELLH + CELLH)));
        float dzz = fmaxf(0.0f, fmaxf((float)z * CELLH - qz, qz - ((float)z * CELLH + CELLH)));
        if (dxx * dxx + dyy * dyy + dzz * dzz > worst_d + 4e-6f) continue;
        processCell((z * GRIDD + y) * GRIDD + x);
    }

    {
        float g = CUDART_INF_F;
        if (cx - 1 > 0)         g = fminf(g, qx - (float)(cx - 1) * CELLH);
        if (cx + 1 < GRIDD - 1) g = fminf(g, (float)(cx + 2) * CELLH - qx);
        if (cy - 1 > 0)         g = fminf(g, qy - (float)(cy - 1) * CELLH);
        if (cy + 1 < GRIDD - 1) g = fminf(g, (float)(cy + 2) * CELLH - qy);
        if (cz - 1 > 0)         g = fminf(g, qz - (float)(cz - 1) * CELLH);
        if (cz + 1 < GRIDD - 1) g = fminf(g, (float)(cz + 2) * CELLH - qz);
        if (worst_d + 4e-6f < g * g) goto done;
    }

    {
        int maxm = cx; if (GRIDD - 1 - cx > maxm) maxm = GRIDD - 1 - cx;
        if (cy > maxm) maxm = cy; if (GRIDD - 1 - cy > maxm) maxm = GRIDD - 1 - cy;
        if (cz > maxm) maxm = cz; if (GRIDD - 1 - cz > maxm) maxm = GRIDD - 1 - cz;

        for (int m = 2; m <= maxm; m++) {
            int zlo = cz - m < 0 ? 0 : cz - m;
            int zhi = cz + m > GRIDD - 1 ? GRIDD - 1 : cz + m;
            for (int z = zlo; z <= zhi; z++) {
                int adz = z - cz; adz = adz < 0 ? -adz : adz;
                float lo = (float)z * CELLH, hi = lo + CELLH;
                float dz = fmaxf(0.0f, fmaxf(lo - qz, qz - hi));
                float dz2 = dz * dz;
                int ylo = cy - m < 0 ? 0 : cy - m;
                int yhi = cy + m > GRIDD - 1 ? GRIDD - 1 : cy + m;
                for (int y = ylo; y <= yhi; y++) {
                    int ady = y - cy; ady = ady < 0 ? -ady : ady;
                    float lyo = (float)y * CELLH, lyh = lyo + CELLH;
                    float dy = fmaxf(0.0f, fmaxf(lyo - qy, qy - lyh));
                    float dyz2 = dz2 + dy * dy;
                    if (dyz2 > worst_d + 4e-6f) continue;
                    int xlo = cx - m < 0 ? 0 : cx - m;
                    int xhi = cx + m > GRIDD - 1 ? GRIDD - 1 : cx + m;
                    for (int x = xlo; x <= xhi; x++) {
                        int adx = x - cx; adx = adx < 0 ? -adx : adx;
                        int cheb = adx > ady ? adx : ady;
                        if (adz > cheb) cheb = adz;
                        if (cheb != m) continue;
                        float lxo = (float)x * CELLH, lxh = lxo + CELLH;
                        float dx = fmaxf(0.0f, fmaxf(lxo - qx, qx - lxh));
                        if (dyz2 + dx * dx > worst_d + 4e-6f) continue;
                        processCell((z * GRIDD + y) * GRIDD + x);
                    }
                }
            }
            float g = CUDART_INF_F;
            if (cx - m > 0)         g = fminf(g, qx - (float)(cx - m) * CELLH);
            if (cx + m < GRIDD - 1) g = fminf(g, (float)(cx + m + 1) * CELLH - qx);
            if (cy - m > 0)         g = fminf(g, qy - (float)(cy - m) * CELLH);
            if (cy + m < GRIDD - 1) g = fminf(g, (float)(cy + m + 1) * CELLH - qy);
            if (cz - m > 0)         g = fminf(g, qz - (float)(cz - m) * CELLH);
            if (cz + m < GRIDD - 1) g = fminf(g, (float)(cz + m + 1) * CELLH - qz);
            if (worst_d + 4e-6f < g * g) break;
        }
    }

done:
#pragma unroll
    for (int j = 0; j < KNNK; j++) d_key[(size_t)t * KNNK + j] = sKV[j * 64 + tid];
}

// ---------------- sortK: warp-per-point register bitonic sorts (grid-sorted order) ----------------
__device__ __forceinline__ void ceA(unsigned long long& h, unsigned& l, int dl, bool keep_min) {
    unsigned long long oh = __shfl_xor_sync(0xFFFFFFFFu, h, dl);
    unsigned ol = __shfl_xor_sync(0xFFFFFFFFu, l, dl);
    bool mine_le = (h < oh) || (h == oh && l <= ol);
    if (mine_le != keep_min) { h = oh; l = ol; }
}
__device__ __forceinline__ void ceB(unsigned long long& h, int dl, bool keep_min) {
    unsigned long long oh = __shfl_xor_sync(0xFFFFFFFFu, h, dl);
    bool mine_le = (h <= oh);
    if (mine_le != keep_min) h = oh;
}

__global__ __launch_bounds__(256) void sortK(const float* __restrict__ cen) {
    int tid = threadIdx.x;
    int lane = tid & 31;
    int wrp = tid >> 5;
    int sp = blockIdx.x * 8 + wrp;

    float4 q = d_sorted[sp];
    float qx = q.x, qy = q.y, qz = q.z;

    const int e0 = 2 * lane, e1 = 2 * lane + 1;
    unsigned long long h0 = ~0ULL, h1 = ~0ULL;
    unsigned l0 = 0xFFFFFFFFu, l1 = 0xFFFFFFFFu;

#pragma unroll
    for (int s = 0; s < 2; s++) {
        int e = s ? e1 : e0;
        if (e < KNNK) {
            unsigned long long k = d_key[(size_t)sp * KNNK + e];
            unsigned id = (unsigned)(k & 0xFFFFull);
            unsigned d32 = (unsigned)(k >> 16);
            float x = __fsub_rn(cen[3 * id], qx);
            float y = __fsub_rn(cen[3 * id + 1], qy);
            float z = __fsub_rn(cen[3 * id + 2], qz);
            float rx = __fmaf_rn(z, -0.5f,    __fmaf_rn(y, 0.7071f, __fmul_rn(x,  0.5f)));
            float ry = __fmaf_rn(z,  0.5f,    __fmaf_rn(y, 0.7071f, __fmul_rn(x, -0.5f)));
            float rz = __fmaf_rn(z,  0.7071f, __fmul_rn(x, 0.7071f));
            float rho = __fsqrt_rn(sumsq_rn(rx, ry, rz));
            unsigned long long h = ((unsigned long long)mapf(rho) << 32) | (unsigned long long)d32;
            if (s) { h1 = h; l1 = id; } else { h0 = h; l0 = id; }
        }
    }

#pragma unroll
    for (int k = 2; k <= 64; k <<= 1) {
        bool asc = ((lane & (k >> 1)) == 0);
#pragma unroll
        for (int j = k >> 1; j >= 2; j >>= 1) {
            int dl = j >> 1;
            bool km = (((lane & dl) == 0) == asc);
            ceA(h0, l0, dl, km);
            ceA(h1, l1, dl, km);
        }
        bool r0_le = (h0 < h1) || (h0 == h1 && l0 <= l1);
        if (r0_le != asc) {
            unsigned long long th = h0; h0 = h1; h1 = th;
            unsigned tl = l0; l0 = l1; l1 = tl;
        }
    }

    unsigned long long b0 = ~0ULL, b1 = ~0ULL;
#pragma unroll
    for (int s = 0; s < 2; s++) {
        int e = s ? e1 : e0;
        unsigned id = (s ? l1 : l0) & 0xFFFFu;
        if (e < KNNK) {
            float x = __fsub_rn(cen[3 * id], qx);
            float y = __fsub_rn(cen[3 * id + 1], qy);
            float z = __fsub_rn(cen[3 * id + 2], qz);
            float rx = __fmaf_rn(z, -0.5f, __fmaf_rn(y, 0.7071f, __fmul_rn(x,  0.5f)));
            float ry = __fmaf_rn(z,  0.5f, __fmaf_rn(y, 0.7071f, __fmul_rn(x, -0.5f)));
            float phi = __fadd_rn(__fdiv_rn(atan2f(ry, rx), TWO_PI_F), 0.5f);
            unsigned long long seg = (e < 9) ? 0ULL : (e < 27) ? 1ULL : 2ULL;
            unsigned long long b = (seg << 54)
                                 | ((unsigned long long)mapf(phi) << 22)
                                 | ((unsigned long long)e << 16)
                                 | (unsigned long long)id;
            if (s) b1 = b; else b0 = b;
        }
    }

#pragma unroll
    for (int k = 2; k <= 64; k <<= 1) {
        bool asc = ((lane & (k >> 1)) == 0);
#pragma unroll
        for (int j = k >> 1; j >= 2; j >>= 1) {
            int dl = j >> 1;
            bool km = (((lane & dl) == 0) == asc);
            ceB(b0, dl, km);
            ceB(b1, dl, km);
        }
        if ((b0 <= b1) != asc) {
            unsigned long long tb = b0; b0 = b1; b1 = tb;
        }
    }

    if (e0 < KNNK) d_idx16[(size_t)sp * KNNK + e0] = (unsigned short)(b0 & 0xFFFFull);
    if (e1 < KNNK) d_idx16[(size_t)sp * KNNK + e1] = (unsigned short)(b1 & 0xFFFFull);
}

// ---------------- mlpK: 2 threads/point (27 triangles each), single pass, rare fixup ----------------
__global__ __launch_bounds__(256) void mlpK(const float* __restrict__ cen,
                                            const float* __restrict__ W1,
                                            const float* __restrict__ b1) {
    __shared__ float sW1[100], sb1[10];
    __shared__ float sWS[8][20];
    __shared__ unsigned sBadX[256];
    int tid = threadIdx.x;
    if (tid < 100) sW1[tid] = W1[tid];
    if (tid < 10) sb1[tid] = b1[tid];
    __syncthreads();

    int half = tid >> 7;                 // 0: t in [0,27), 1: t in [27,54)
    int lp = tid & 127;                  // local point
    int sp = blockIdx.x * 128 + lp;
    float4 q = d_sorted[sp];
    float qx = q.x, qy = q.y, qz = q.z;

    auto idxAt = [&](int i) -> int { return (int)d_idx16[(size_t)sp * KNNK + i]; };
    auto nextT = [](int t) -> int {
        int base, len;
        if (t < 9) { base = 0; len = 9; }
        else if (t < 27) { base = 9; len = 18; }
        else { base = 27; len = 27; }
        int loc = t - base + 1;
        return base + (loc == len ? 0 : loc);
    };

    // pm: duplicated evaluation of triangle 0's cross sign (bit-identical in both halves)
    float pm;
    {
        int na = idxAt(0), nb = idxAt(1);       // nextT(0) == 1
        float e1x = __fsub_rn(cen[3 * na], qx);
        float e1y = __fsub_rn(cen[3 * na + 1], qy);
        float e1z = __fsub_rn(cen[3 * na + 2], qz);
        float e2x = __fsub_rn(cen[3 * nb], qx);
        float e2y = __fsub_rn(cen[3 * nb + 1], qy);
        float e2z = __fsub_rn(cen[3 * nb + 2], qz);
        float nx = __fsub_rn(__fmul_rn(e1y, e2z), __fmul_rn(e1z, e2y));
        float ny = __fsub_rn(__fmul_rn(e1z, e2x), __fmul_rn(e1x, e2z));
        float nz = __fsub_rn(__fmul_rn(e1x, e2y), __fmul_rn(e1y, e2x));
        float nl = __fsqrt_rn(sumsq_rn(nx, ny, nz));
        float ux = (nl == 0.0f) ? 0.0f : __fdiv_rn(nx, nl);
        pm = (ux > 0.0f) ? 1.0f : -1.0f;
    }

    int tBeg = half * 27;
    unsigned badm27 = 0u;

    float s0[10], s1[10];
#pragma unroll
    for (int c = 0; c < 10; c++) { s0[c] = 0.0f; s1[c] = 0.0f; }

    for (int k27 = 0; k27 < 27; k27++) {
        int t = tBeg + k27;
        int na = idxAt(t), nb = idxAt(nextT(t));
        float e1x = __fsub_rn(cen[3 * na], qx);
        float e1y = __fsub_rn(cen[3 * na + 1], qy);
        float e1z = __fsub_rn(cen[3 * na + 2], qz);
        float e2x = __fsub_rn(cen[3 * nb], qx);
        float e2y = __fsub_rn(cen[3 * nb + 1], qy);
        float e2z = __fsub_rn(cen[3 * nb + 2], qz);
        float nx = __fsub_rn(__fmul_rn(e1y, e2z), __fmul_rn(e1z, e2y));
        float ny = __fsub_rn(__fmul_rn(e1z, e2x), __fmul_rn(e1x, e2z));
        float nz = __fsub_rn(__fmul_rn(e1x, e2y), __fmul_rn(e1y, e2x));
        float nl = __fsqrt_rn(sumsq_rn(nx, ny, nz));
        bool bad = (nl == 0.0f);
        float ux, uy, uz;
        if (bad) { ux = 0.0f; uy = 0.0f; uz = 0.0f; }
        else {
            ux = __fdiv_rn(nx, nl); uy = __fdiv_rn(ny, nl); uz = __fdiv_rn(nz, nl);
        }
        ux = __fmul_rn(ux, pm); uy = __fmul_rn(uy, pm); uz = __fmul_rn(uz, pm);
        float ccx = __fdiv_rn(__fadd_rn(e1x, e2x), 3.0f);
        float ccy = __fdiv_rn(__fadd_rn(e1y, e2y), 3.0f);
        float ccz = __fdiv_rn(__fadd_rn(e1z, e2z), 3.0f);
        float pos = __fdiv_rn(
            __fadd_rn(__fadd_rn(__fmul_rn(ux, ccx), __fmul_rn(uy, ccy)), __fmul_rn(uz, ccz)),
            SQRT3_F);

        float rho = __fsqrt_rn(sumsq_rn(ccx, ccy, ccz));
        float phi = __fadd_rn(__fdiv_rn(atan2f(ccy, ccx), TWO_PI_F), 0.5f);
        float theta;
        if (rho == 0.0f) theta = 0.0f;
        else {
            float r = __fdiv_rn(ccz, rho);
            r = fminf(1.0f, fmaxf(-1.0f, r));
            theta = __fdiv_rn(acosf(r), PI_F);
        }
        float f[10];
        f[0] = rho; f[1] = theta; f[2] = phi;
        f[3] = ux; f[4] = uy; f[5] = uz;
        f[6] = pos;
        f[7] = ccx; f[8] = ccy; f[9] = ccz;

        int chBase = t * 10;
#pragma unroll
        for (int c = 0; c < 10; c++) {
            float acc = 0.0f;
#pragma unroll
            for (int k = 0; k < 10; k++) acc += f[k] * sW1[c * 10 + k];
            float h = acc + sb1[c];
            d_h[(size_t)(chBase + c) * N_PTS + sp] = h;
            s0[c] += h;
            s1[c] += h * h;
        }

        if (bad) badm27 |= (1u << k27);
    }

    // exchange bad masks between halves of the same point
    sBadX[tid] = badm27;
    __syncthreads();
    unsigned otherB = sBadX[tid ^ 128];

    if (badm27 != 0u) {
        unsigned m0 = half ? otherB : badm27;     // half-0 mask (t 0..26)
        unsigned m1 = half ? badm27 : otherB;     // half-1 mask (t 27..53)
        unsigned long long gbad = (unsigned long long)m0 |
                                  ((unsigned long long)m1 << 27);
        unsigned long long good = ~gbad & ((1ULL << 54) - 1ULL);
        int first = good ? (__ffsll((long long)good) - 1) : 0;

        // evaluate first-good triangle's features (pm already final)
        float fux, fuy, fuz, fcx, fcy, fcz, fpos;
        {
            int na = idxAt(first), nb = idxAt(nextT(first));
            float e1x = __fsub_rn(cen[3 * na], qx);
            float e1y = __fsub_rn(cen[3 * na + 1], qy);
            float e1z = __fsub_rn(cen[3 * na + 2], qz);
            float e2x = __fsub_rn(cen[3 * nb], qx);
            float e2y = __fsub_rn(cen[3 * nb + 1], qy);
            float e2z = __fsub_rn(cen[3 * nb + 2], qz);
            float nx = __fsub_rn(__fmul_rn(e1y, e2z), __fmul_rn(e1z, e2y));
            float ny = __fsub_rn(__fmul_rn(e1z, e2x), __fmul_rn(e1x, e2z));
            float nz = __fsub_rn(__fmul_rn(e1x, e2y), __fmul_rn(e1y, e2x));
            float nl = __fsqrt_rn(sumsq_rn(nx, ny, nz));
            bool bad = (nl == 0.0f);
            if (bad) { fux = 0.0f; fuy = 0.0f; fuz = 0.0f; }
            else {
                fux = __fdiv_rn(nx, nl); fuy = __fdiv_rn(ny, nl); fuz = __fdiv_rn(nz, nl);
            }
            fux = __fmul_rn(fux, pm); fuy = __fmul_rn(fuy, pm); fuz = __fmul_rn(fuz, pm);
            fcx = __fdiv_rn(__fadd_rn(e1x, e2x), 3.0f);
            fcy = __fdiv_rn(__fadd_rn(e1y, e2y), 3.0f);
            fcz = __fdiv_rn(__fadd_rn(e1z, e2z), 3.0f);
            fpos = __fdiv_rn(
                __fadd_rn(__fadd_rn(__fmul_rn(fux, fcx), __fmul_rn(fuy, fcy)), __fmul_rn(fuz, fcz)),
                SQRT3_F);
        }
        unsigned m = badm27;
        while (m) {
            int k27 = __ffs((int)m) - 1;
            m &= m - 1u;
            int t = tBeg + k27;
            int na = idxAt(t), nb = idxAt(nextT(t));
            float e1x = __fsub_rn(cen[3 * na], qx);
            float e1y = __fsub_rn(cen[3 * na + 1], qy);
            float e1z = __fsub_rn(cen[3 * na + 2], qz);
            float e2x = __fsub_rn(cen[3 * nb], qx);
            float e2y = __fsub_rn(cen[3 * nb + 1], qy);
            float e2z = __fsub_rn(cen[3 * nb + 2], qz);
            float ccx = __fdiv_rn(__fadd_rn(e1x, e2x), 3.0f);
            float ccy = __fdiv_rn(__fadd_rn(e1y, e2y), 3.0f);
            float ccz = __fdiv_rn(__fadd_rn(e1z, e2z), 3.0f);
            float rho = __fsqrt_rn(sumsq_rn(ccx, ccy, ccz));
            float phi = __fadd_rn(__fdiv_rn(atan2f(ccy, ccx), TWO_PI_F), 0.5f);
            float theta;
            if (rho == 0.0f) theta = 0.0f;
            else {
                float r = __fdiv_rn(ccz, rho);
                r = fminf(1.0f, fmaxf(-1.0f, r));
                theta = __fdiv_rn(acosf(r), PI_F);
            }
            float f[10];
            f[0] = rho; f[1] = theta; f[2] = phi;     // polar from OWN centroid
            f[3] = fux; f[4] = fuy; f[5] = fuz;       // replaced from first
            f[6] = fpos;
            f[7] = fcx; f[8] = fcy; f[9] = fcz;

            int chBase = t * 10;
#pragma unroll
            for (int c = 0; c < 10; c++) {
                float acc = 0.0f;
#pragma unroll
                for (int k = 0; k < 10; k++) acc += f[k] * sW1[c * 10 + k];
                float hn = acc + sb1[c];
                size_t off = (size_t)(chBase + c) * N_PTS + sp;
                float ho = d_h[off];
                d_h[off] = hn;
                s0[c] = s0[c] - ho + hn;
                s1[c] = s1[c] - ho * ho + hn * hn;
            }
        }
    }

    int lane = tid & 31, wrp = tid >> 5;
#pragma unroll
    for (int v = 0; v < 20; v++) {
        float a = (v < 10) ? s0[v] : s1[v - 10];
#pragma unroll
        for (int off = 16; off > 0; off >>= 1) a += __shfl_down_sync(0xFFFFFFFFu, a, off);
        if (lane == 0) sWS[wrp][v] = a;
    }
    __syncthreads();
    if (tid < 20) {
        float a = 0.0f;
#pragma unroll
        for (int w = 0; w < 8; w++) a += sWS[w][tid];
        d_part[blockIdx.x * 20 + tid] = a;
    }
}

// ---------------- BN finalize ----------------
__global__ __launch_bounds__(640) void bnK(const float* __restrict__ gamma,
                                           const float* __restrict__ beta) {
    __shared__ float S[20];
    int tid = threadIdx.x;
    int w = tid / 32, l = tid % 32;
    float a = 0.0f;
    for (int k = l; k < MBLK; k += 32) a += d_part[k * 20 + w];
#pragma unroll
    for (int off = 16; off > 0; off >>= 1) a += __shfl_down_sync(0xFFFFFFFFu, a, off);
    if (l == 0) S[w] = a;
    __syncthreads();
    if (tid < 10) {
        const double M = (double)N_PTS * 54.0;
        double mu = (double)S[tid] / M;
        double var = (double)S[tid + 10] / M - mu * mu;
        if (var < 0.0) var = 0.0;
        float sc = gamma[tid] * rsqrtf((float)var + 1e-5f);
        d_bn[tid] = sc;
        d_bn[10 + tid] = beta[tid] - (float)mu * sc;
    }
}

// ---------------- BN affine + relu + layer2 + sum over 54 (sorted order, scatter out) ----------------
__global__ __launch_bounds__(256) void outK(const float* __restrict__ W2,
                                            const float* __restrict__ b2,
                                            float* __restrict__ out) {
    __shared__ float sa[10], sb[10], sW2[100], sb2[10];
    int tid = threadIdx.x;
    if (tid < 10) { sa[tid] = d_bn[tid]; sb[tid] = d_bn[10 + tid]; sb2[tid] = b2[tid]; }
    if (tid < 100) sW2[tid] = W2[tid];
    __syncthreads();

    int sp = blockIdx.x * blockDim.x + tid;
    float acc[10];
#pragma unroll
    for (int c = 0; c < 10; c++) acc[c] = 0.0f;
    for (int t = 0; t < 54; t++) {
#pragma unroll
        for (int c = 0; c < 10; c++) {
            float v = d_h[(size_t)(t * 10 + c) * N_PTS + sp] * sa[c] + sb[c];
            v = fmaxf(v, 0.0f);
            acc[c] += v;
        }
    }
    int p = d_sid[sp];
#pragma unroll
    for (int c = 0; c < 10; c++) {
        float o = 54.0f * sb2[c];
#pragma unroll
        for (int j = 0; j < 10; j++) o += acc[j] * sW2[c * 10 + j];
        out[p * 10 + c] = o;
    }
}

// ---------------- launch ----------------
extern "C" void kernel_launch(void* const* d_in, const int* in_sizes, int n_in,
                              void* d_out, int out_size) {
    const float* center = (const float*)d_in[0];
    const float* W1 = (const float*)d_in[2];
    const float* b1 = (const float*)d_in[3];
    const float* gamma = (const float*)d_in[4];
    const float* beta = (const float*)d_in[5];
    const float* W2 = (const float*)d_in[6];
    const float* b2 = (const float*)d_in[7];
    float* out = (float*)d_out;

    void* cntPtr = nullptr;
    cudaGetSymbolAddress(&cntPtr, d_cnt);
    cudaMemsetAsync(cntPtr, 0, NCELL * sizeof(int), 0);

    countK<<<256, 256>>>(center);
    scanK<<<1, 1024>>>();
    scatterK<<<256, 256>>>(center);
    knnK<<<1024, 64>>>();
    sortK<<<8192, 256>>>(center);
    mlpK<<<MBLK, 256>>>(center, W1, b1);
    bnK<<<1, 640>>>(gamma, beta);
    outK<<<256, 256>>>(W2, b2, out);
}

// round 16
// speedup vs baseline: 1.3729x; 1.0680x over previous
#include <cuda_runtime.h>
#include <math_constants.h>

#define N_PTS 65536
#define KNNK 54
#define GRIDD 16
#define NCELL 4096
#define CELLH 0.0625f
#define MBLK 256     // mlpK: 256 blocks x 256 threads

#define TWO_PI_F 6.28318530717958647692f
#define PI_F     3.14159265358979323846f
#define SQRT3_F  1.73205080756887729353f

// ---------------- scratch (static device memory; no allocation) ----------------
__device__ float4 d_sorted[N_PTS];      // (x, y, z, psq) in grid-sorted order
__device__ int d_sid[N_PTS];            // original point id per sorted position
__device__ int d_cellStart[NCELL + 1];
__device__ int d_cellPtr[NCELL];
__device__ int d_cnt[NCELL];
__device__ unsigned long long d_key[N_PTS * KNNK];   // (mapped-d<<16)|orig_id, [sp][slot]
__device__ unsigned short d_idx16[N_PTS * KNNK];     // sorted neighbor orig-ids [sp][slot]
__device__ float d_h[N_PTS * KNNK * 10];             // [ch][sp]
__device__ float d_part[MBLK * 20];
__device__ float d_bn[20];

// canonical (+,+,+) octant: 27 cell offsets sorted by min box distance
__constant__ char4 c_ord[27] = {
    { 0, 0, 0, 0},
    { 1, 0, 0, 0}, { 0, 1, 0, 0}, { 0, 0, 1, 0},
    { 1, 1, 0, 0}, { 1, 0, 1, 0}, { 0, 1, 1, 0},
    { 1, 1, 1, 0},
    {-1, 0, 0, 0}, { 0,-1, 0, 0}, { 0, 0,-1, 0},
    {-1, 1, 0, 0}, {-1, 0, 1, 0}, { 1,-1, 0, 0},
    { 0,-1, 1, 0}, { 1, 0,-1, 0}, { 0, 1,-1, 0},
    {-1, 1, 1, 0}, { 1,-1, 1, 0}, { 1, 1,-1, 0},
    {-1,-1, 0, 0}, {-1, 0,-1, 0}, { 0,-1,-1, 0},
    {-1,-1, 1, 0}, {-1, 1,-1, 0}, { 1,-1,-1, 0},
    {-1,-1,-1, 0}
};

__device__ __forceinline__ int cellCoord(float v) {
    int c = (int)floorf(v * 16.0f);
    c = c < 0 ? 0 : c;
    return c > (GRIDD - 1) ? (GRIDD - 1) : c;
}

__device__ __forceinline__ float sumsq_rn(float x, float y, float z) {
    return __fadd_rn(__fadd_rn(__fmul_rn(x, x), __fmul_rn(y, y)), __fmul_rn(z, z));
}

__device__ __forceinline__ float dot3_fma(float ax, float ay, float az,
                                          float bx, float by, float bz) {
    return __fmaf_rn(az, bz, __fmaf_rn(ay, by, __fmul_rn(ax, bx)));
}

__device__ __forceinline__ unsigned mapf(float d) {
    unsigned u = __float_as_uint(d);
    return (u & 0x80000000u) ? ~u : (u | 0x80000000u);
}
__device__ __forceinline__ float unmapf(unsigned m) {
    unsigned u = (m & 0x80000000u) ? (m & 0x7FFFFFFFu) : ~m;
    return __uint_as_float(u);
}

// ---------------- grid build ----------------
__global__ void countK(const float* __restrict__ c) {
    int i = blockIdx.x * blockDim.x + threadIdx.x;
    if (i >= N_PTS) return;
    int cx = cellCoord(c[3 * i]);
    int cy = cellCoord(c[3 * i + 1]);
    int cz = cellCoord(c[3 * i + 2]);
    atomicAdd(&d_cnt[(cz * GRIDD + cy) * GRIDD + cx], 1);
}

__global__ __launch_bounds__(1024) void scanK() {
    __shared__ int s[1024];
    int t = threadIdx.x;
    int v0 = d_cnt[4 * t], v1 = d_cnt[4 * t + 1], v2 = d_cnt[4 * t + 2], v3 = d_cnt[4 * t + 3];
    int tot = v0 + v1 + v2 + v3;
    s[t] = tot;
    __syncthreads();
    for (int off = 1; off < 1024; off <<= 1) {
        int x = (t >= off) ? s[t - off] : 0;
        __syncthreads();
        s[t] += x;
        __syncthreads();
    }
    int excl = s[t] - tot;
    d_cellStart[4 * t] = excl;
    d_cellStart[4 * t + 1] = excl + v0;
    d_cellStart[4 * t + 2] = excl + v0 + v1;
    d_cellStart[4 * t + 3] = excl + v0 + v1 + v2;
    d_cellPtr[4 * t] = excl;
    d_cellPtr[4 * t + 1] = excl + v0;
    d_cellPtr[4 * t + 2] = excl + v0 + v1;
    d_cellPtr[4 * t + 3] = excl + v0 + v1 + v2;
    if (t == 1023) d_cellStart[NCELL] = s[1023];
}

__global__ void scatterK(const float* __restrict__ c) {
    int i = blockIdx.x * blockDim.x + threadIdx.x;
    if (i >= N_PTS) return;
    float x = c[3 * i], y = c[3 * i + 1], z = c[3 * i + 2];
    int cid = (cellCoord(z) * GRIDD + cellCoord(y)) * GRIDD + cellCoord(x);
    int pos = atomicAdd(&d_cellPtr[cid], 1);
    d_sorted[pos] = make_float4(x, y, z, sumsq_rn(x, y, z));
    d_sid[pos] = i;
}

// ---------------- KNN: u64 smem top-54, tracked worst group, 4-wide MLP batching ----------------
__global__ __launch_bounds__(64) void knnK() {
    __shared__ unsigned long long sKV[KNNK * 64];
    int tid = threadIdx.x;
    int t = blockIdx.x * 64 + tid;      // sorted position
    float4 q = d_sorted[t];
    float qx = q.x, qy = q.y, qz = q.z;
    float qsq = q.w;
    int cx = cellCoord(qx), cy = cellCoord(qy), cz = cellCoord(qz);

    int count = 0;
    unsigned long long gm[9];
    unsigned long long wkey = 0xFFFFFFFFFFFFFFFFull;
    int wg = 0;
    float worst_d = CUDART_INF_F;

    auto accept = [&](float d, int p) {
        unsigned pi = (unsigned)d_sid[p];     // ORIGINAL id: tie-break semantics
        unsigned long long nk = ((unsigned long long)mapf(d) << 16) | pi;
        if (count < KNNK) {
            sKV[count * 64 + tid] = nk;
            count++;
            if (count == KNNK) {
                unsigned long long w = 0ULL; int wgl = 0;
#pragma unroll
                for (int g = 0; g < 9; g++) {
                    unsigned long long gv = 0ULL;
#pragma unroll
                    for (int j = 0; j < 6; j++) {
                        unsigned long long v = sKV[(g * 6 + j) * 64 + tid];
                        if (v > gv) gv = v;
                    }
                    gm[g] = gv;
                    if (gv > w) { w = gv; wgl = g; }
                }
                wkey = w; wg = wgl;
                worst_d = unmapf((unsigned)(w >> 16));
            }
        } else if (nk < wkey) {
            int base = wg * 6;
            unsigned long long m1 = 0ULL, m2 = 0ULL;
            int ms = base;
#pragma unroll
            for (int j = 0; j < 6; j++) {
                unsigned long long v = sKV[(base + j) * 64 + tid];
                if (v > m1) { m2 = m1; m1 = v; ms = base + j; }
                else if (v > m2) m2 = v;
            }
            sKV[ms * 64 + tid] = nk;
            gm[wg] = nk > m2 ? nk : m2;
            unsigned long long w = gm[0]; int wgl = 0;
#pragma unroll
            for (int g = 1; g < 9; g++) if (gm[g] > w) { w = gm[g]; wgl = g; }
            wkey = w; wg = wgl;
            worst_d = unmapf((unsigned)(w >> 16));
        }
    };

    auto processCell = [&](int cid) {
        int s = d_cellStart[cid], e = d_cellStart[cid + 1];
        int p = s;
        for (; p + 4 <= e; p += 4) {
            float4 a0 = d_sorted[p];
            float4 a1 = d_sorted[p + 1];
            float4 a2 = d_sorted[p + 2];
            float4 a3 = d_sorted[p + 3];
            float d0 = __fsub_rn(__fadd_rn(qsq, a0.w),
                                 __fmul_rn(2.0f, dot3_fma(qx, qy, qz, a0.x, a0.y, a0.z)));
            float d1 = __fsub_rn(__fadd_rn(qsq, a1.w),
                                 __fmul_rn(2.0f, dot3_fma(qx, qy, qz, a1.x, a1.y, a1.z)));
            float d2 = __fsub_rn(__fadd_rn(qsq, a2.w),
                                 __fmul_rn(2.0f, dot3_fma(qx, qy, qz, a2.x, a2.y, a2.z)));
            float d3 = __fsub_rn(__fadd_rn(qsq, a3.w),
                                 __fmul_rn(2.0f, dot3_fma(qx, qy, qz, a3.x, a3.y, a3.z)));
            if (d0 <= worst_d) accept(d0, p);
            if (d1 <= worst_d) accept(d1, p + 1);
            if (d2 <= worst_d) accept(d2, p + 2);
            if (d3 <= worst_d) accept(d3, p + 3);
        }
        for (; p < e; p++) {
            float4 a = d_sorted[p];
            float d = __fsub_rn(__fadd_rn(qsq, a.w),
                                __fmul_rn(2.0f, dot3_fma(qx, qy, qz, a.x, a.y, a.z)));
            if (d <= worst_d) accept(d, p);
        }
    };

    int sx = (qx > ((float)cx + 0.5f) * CELLH) ? 1 : -1;
    int sy = (qy > ((float)cy + 0.5f) * CELLH) ? 1 : -1;
    int sz = (qz > ((float)cz + 0.5f) * CELLH) ? 1 : -1;

#pragma unroll 1
    for (int o = 0; o < 27; o++) {
        char4 c = c_ord[o];
        int x = cx + sx * (int)c.x;
        int y = cy + sy * (int)c.y;
        int z = cz + sz * (int)c.z;
        if (((unsigned)x | (unsigned)y | (unsigned)z) > 15u) continue;
        float dxx = fmaxf(0.0f, fmaxf((float)x * CELLH - qx, qx - ((float)x * CELLH + CELLH)));
        float dyy = fmaxf(0.0f, fmaxf((float)y * CELLH - qy, qy - ((float)y * CELLH + CELLH)));
        float dzz = fmaxf(0.0f, fmaxf((float)z * CELLH - qz, qz - ((float)z * CELLH + CELLH)));
        if (dxx * dxx + dyy * dyy + dzz * dzz > worst_d + 4e-6f) continue;
        processCell((z * GRIDD + y) * GRIDD + x);
    }

    {
        float g = CUDART_INF_F;
        if (cx - 1 > 0)         g = fminf(g, qx - (float)(cx - 1) * CELLH);
        if (cx + 1 < GRIDD - 1) g = fminf(g, (float)(cx + 2) * CELLH - qx);
        if (cy - 1 > 0)         g = fminf(g, qy - (float)(cy - 1) * CELLH);
        if (cy + 1 < GRIDD - 1) g = fminf(g, (float)(cy + 2) * CELLH - qy);
        if (cz - 1 > 0)         g = fminf(g, qz - (float)(cz - 1) * CELLH);
        if (cz + 1 < GRIDD - 1) g = fminf(g, (float)(cz + 2) * CELLH - qz);
        if (worst_d + 4e-6f < g * g) goto done;
    }

    {
        int maxm = cx; if (GRIDD - 1 - cx > maxm) maxm = GRIDD - 1 - cx;
        if (cy > maxm) maxm = cy; if (GRIDD - 1 - cy > maxm) maxm = GRIDD - 1 - cy;
        if (cz > maxm) maxm = cz; if (GRIDD - 1 - cz > maxm) maxm = GRIDD - 1 - cz;

        for (int m = 2; m <= maxm; m++) {
            int zlo = cz - m < 0 ? 0 : cz - m;
            int zhi = cz + m > GRIDD - 1 ? GRIDD - 1 : cz + m;
            for (int z = zlo; z <= zhi; z++) {
                int adz = z - cz; adz = adz < 0 ? -adz : adz;
                float lo = (float)z * CELLH, hi = lo + CELLH;
                float dz = fmaxf(0.0f, fmaxf(lo - qz, qz - hi));
                float dz2 = dz * dz;
                int ylo = cy - m < 0 ? 0 : cy - m;
                int yhi = cy + m > GRIDD - 1 ? GRIDD - 1 : cy + m;
                for (int y = ylo; y <= yhi; y++) {
                    int ady = y - cy; ady = ady < 0 ? -ady : ady;
                    float lyo = (float)y * CELLH, lyh = lyo + CELLH;
                    float dy = fmaxf(0.0f, fmaxf(lyo - qy, qy - lyh));
                    float dyz2 = dz2 + dy * dy;
                    if (dyz2 > worst_d + 4e-6f) continue;
                    int xlo = cx - m < 0 ? 0 : cx - m;
                    int xhi = cx + m > GRIDD - 1 ? GRIDD - 1 : cx + m;
                    for (int x = xlo; x <= xhi; x++) {
                        int adx = x - cx; adx = adx < 0 ? -adx : adx;
                        int cheb = adx > ady ? adx : ady;
                        if (adz > cheb) cheb = adz;
                        if (cheb != m) continue;
                        float lxo = (float)x * CELLH, lxh = lxo + CELLH;
                        float dx = fmaxf(0.0f, fmaxf(lxo - qx, qx - lxh));
                        if (dyz2 + dx * dx > worst_d + 4e-6f) continue;
                        processCell((z * GRIDD + y) * GRIDD + x);
                    }
                }
            }
            float g = CUDART_INF_F;
            if (cx - m > 0)         g = fminf(g, qx - (float)(cx - m) * CELLH);
            if (cx + m < GRIDD - 1) g = fminf(g, (float)(cx + m + 1) * CELLH - qx);
            if (cy - m > 0)         g = fminf(g, qy - (float)(cy - m) * CELLH);
            if (cy + m < GRIDD - 1) g = fminf(g, (float)(cy + m + 1) * CELLH - qy);
            if (cz - m > 0)         g = fminf(g, qz - (float)(cz - m) * CELLH);
            if (cz + m < GRIDD - 1) g = fminf(g, (float)(cz + m + 1) * CELLH - qz);
            if (worst_d + 4e-6f < g * g) break;
        }
    }

done:
#pragma unroll
    for (int j = 0; j < KNNK; j++) d_key[(size_t)t * KNNK + j] = sKV[j * 64 + tid];
}

// ---------------- sortK: warp-per-point bitonic sorts, phi carried as payload ----------------
__device__ __forceinline__ void ceA3(unsigned long long& h, unsigned& l, float& p,
                                     int dl, bool keep_min) {
    unsigned long long oh = __shfl_xor_sync(0xFFFFFFFFu, h, dl);
    unsigned ol = __shfl_xor_sync(0xFFFFFFFFu, l, dl);
    float op = __shfl_xor_sync(0xFFFFFFFFu, p, dl);
    bool mine_le = (h < oh) || (h == oh && l <= ol);
    if (mine_le != keep_min) { h = oh; l = ol; p = op; }
}
__device__ __forceinline__ void ceB(unsigned long long& h, int dl, bool keep_min) {
    unsigned long long oh = __shfl_xor_sync(0xFFFFFFFFu, h, dl);
    bool mine_le = (h <= oh);
    if (mine_le != keep_min) h = oh;
}

__global__ __launch_bounds__(256) void sortK(const float* __restrict__ cen) {
    int tid = threadIdx.x;
    int lane = tid & 31;
    int wrp = tid >> 5;
    int sp = blockIdx.x * 8 + wrp;

    float4 q = d_sorted[sp];
    float qx = q.x, qy = q.y, qz = q.z;

    const int e0 = 2 * lane, e1 = 2 * lane + 1;
    unsigned long long h0 = ~0ULL, h1 = ~0ULL;
    unsigned l0 = 0xFFFFFFFFu, l1 = 0xFFFFFFFFu;
    float p0 = 0.0f, p1 = 0.0f;    // phi payloads

    // phase A key build: rho key + phi payload (phi computed once, here)
#pragma unroll
    for (int s = 0; s < 2; s++) {
        int e = s ? e1 : e0;
        if (e < KNNK) {
            unsigned long long k = d_key[(size_t)sp * KNNK + e];
            unsigned id = (unsigned)(k & 0xFFFFull);
            unsigned d32 = (unsigned)(k >> 16);
            float x = __fsub_rn(cen[3 * id], qx);
            float y = __fsub_rn(cen[3 * id + 1], qy);
            float z = __fsub_rn(cen[3 * id + 2], qz);
            float rx = __fmaf_rn(z, -0.5f,    __fmaf_rn(y, 0.7071f, __fmul_rn(x,  0.5f)));
            float ry = __fmaf_rn(z,  0.5f,    __fmaf_rn(y, 0.7071f, __fmul_rn(x, -0.5f)));
            float rz = __fmaf_rn(z,  0.7071f, __fmul_rn(x, 0.7071f));
            float rho = __fsqrt_rn(sumsq_rn(rx, ry, rz));
            float phi = __fadd_rn(__fdiv_rn(atan2f(ry, rx), TWO_PI_F), 0.5f);
            unsigned long long h = ((unsigned long long)mapf(rho) << 32) | (unsigned long long)d32;
            if (s) { h1 = h; l1 = id; p1 = phi; } else { h0 = h; l0 = id; p0 = phi; }
        }
    }

    // Sort A: bitonic over 64 virtual elements, carrying (id, phi)
#pragma unroll
    for (int k = 2; k <= 64; k <<= 1) {
        bool asc = ((lane & (k >> 1)) == 0);
#pragma unroll
        for (int j = k >> 1; j >= 2; j >>= 1) {
            int dl = j >> 1;
            bool km = (((lane & dl) == 0) == asc);
            ceA3(h0, l0, p0, dl, km);
            ceA3(h1, l1, p1, dl, km);
        }
        bool r0_le = (h0 < h1) || (h0 == h1 && l0 <= l1);
        if (r0_le != asc) {
            unsigned long long th = h0; h0 = h1; h1 = th;
            unsigned tl = l0; l0 = l1; l1 = tl;
            float tp = p0; p0 = p1; p1 = tp;
        }
    }

    // phase B keys from carried phi (no memory access, no atan2)
    unsigned long long b0 = ~0ULL, b1 = ~0ULL;
    if (e0 < KNNK) {
        unsigned long long seg = (e0 < 9) ? 0ULL : (e0 < 27) ? 1ULL : 2ULL;
        b0 = (seg << 54)
           | ((unsigned long long)mapf(p0) << 22)
           | ((unsigned long long)e0 << 16)
           | (unsigned long long)(l0 & 0xFFFFu);
    }
    if (e1 < KNNK) {
        unsigned long long seg = (e1 < 9) ? 0ULL : (e1 < 27) ? 1ULL : 2ULL;
        b1 = (seg << 54)
           | ((unsigned long long)mapf(p1) << 22)
           | ((unsigned long long)e1 << 16)
           | (unsigned long long)(l1 & 0xFFFFu);
    }

    // Sort B: segmented stable phi sort
#pragma unroll
    for (int k = 2; k <= 64; k <<= 1) {
        bool asc = ((lane & (k >> 1)) == 0);
#pragma unroll
        for (int j = k >> 1; j >= 2; j >>= 1) {
            int dl = j >> 1;
            bool km = (((lane & dl) == 0) == asc);
            ceB(b0, dl, km);
            ceB(b1, dl, km);
        }
        if ((b0 <= b1) != asc) {
            unsigned long long tb = b0; b0 = b1; b1 = tb;
        }
    }

    if (e0 < KNNK) d_idx16[(size_t)sp * KNNK + e0] = (unsigned short)(b0 & 0xFFFFull);
    if (e1 < KNNK) d_idx16[(size_t)sp * KNNK + e1] = (unsigned short)(b1 & 0xFFFFull);
}

// ---------------- mlpK: single pass, edge reuse (1 new gather per triangle), rare fixup ----------------
__global__ __launch_bounds__(256) void mlpK(const float* __restrict__ cen,
                                            const float* __restrict__ W1,
                                            const float* __restrict__ b1) {
    __shared__ float sW1[100], sb1[10];
    __shared__ float sWS[8][20];
    int tid = threadIdx.x;
    if (tid < 100) sW1[tid] = W1[tid];
    if (tid < 10) sb1[tid] = b1[tid];
    __syncthreads();

    int sp = blockIdx.x * 256 + tid;
    float4 q = d_sorted[sp];
    float qx = q.x, qy = q.y, qz = q.z;

    auto idxAt = [&](int i) -> int { return (int)d_idx16[(size_t)sp * KNNK + i]; };
    auto nextT = [](int t) -> int {
        int base, len;
        if (t < 9) { base = 0; len = 9; }
        else if (t < 27) { base = 9; len = 18; }
        else { base = 27; len = 27; }
        int loc = t - base + 1;
        return base + (loc == len ? 0 : loc);
    };
    auto loadRel = [&](int id, float& ex, float& ey, float& ez) {
        ex = __fsub_rn(cen[3 * id], qx);
        ey = __fsub_rn(cen[3 * id + 1], qy);
        ez = __fsub_rn(cen[3 * id + 2], qz);
    };

    float pm = 1.0f;
    unsigned long long badm = 0ULL;
    int first = -1;

    float s0[10], s1[10];
#pragma unroll
    for (int c = 0; c < 10; c++) { s0[c] = 0.0f; s1[c] = 0.0f; }

    // single pass over 3 segments; e2(t) == e1(t+1) within a segment
    for (int seg = 0; seg < 3; seg++) {
        int base = (seg == 0) ? 0 : (seg == 1) ? 9 : 27;
        int len  = (seg == 0) ? 9 : (seg == 1) ? 18 : 27;
        float fx, fy, fz;                       // segment-first edge (for wrap)
        loadRel(idxAt(base), fx, fy, fz);
        float e1x = fx, e1y = fy, e1z = fz;
        for (int loc = 0; loc < len; loc++) {
            int t = base + loc;
            float e2x, e2y, e2z;
            if (loc == len - 1) { e2x = fx; e2y = fy; e2z = fz; }
            else loadRel(idxAt(t + 1), e2x, e2y, e2z);

            float nx = __fsub_rn(__fmul_rn(e1y, e2z), __fmul_rn(e1z, e2y));
            float ny = __fsub_rn(__fmul_rn(e1z, e2x), __fmul_rn(e1x, e2z));
            float nz = __fsub_rn(__fmul_rn(e1x, e2y), __fmul_rn(e1y, e2x));
            float nl = __fsqrt_rn(sumsq_rn(nx, ny, nz));
            bool bad = (nl == 0.0f);
            float ux, uy, uz;
            if (bad) { ux = 0.0f; uy = 0.0f; uz = 0.0f; }
            else {
                ux = __fdiv_rn(nx, nl); uy = __fdiv_rn(ny, nl); uz = __fdiv_rn(nz, nl);
            }
            if (t == 0) pm = (ux > 0.0f) ? 1.0f : -1.0f;
            ux = __fmul_rn(ux, pm); uy = __fmul_rn(uy, pm); uz = __fmul_rn(uz, pm);
            float ccx = __fdiv_rn(__fadd_rn(e1x, e2x), 3.0f);
            float ccy = __fdiv_rn(__fadd_rn(e1y, e2y), 3.0f);
            float ccz = __fdiv_rn(__fadd_rn(e1z, e2z), 3.0f);
            float pos = __fdiv_rn(
                __fadd_rn(__fadd_rn(__fmul_rn(ux, ccx), __fmul_rn(uy, ccy)), __fmul_rn(uz, ccz)),
                SQRT3_F);

            float rho = __fsqrt_rn(sumsq_rn(ccx, ccy, ccz));
            float phi = __fadd_rn(__fdiv_rn(atan2f(ccy, ccx), TWO_PI_F), 0.5f);
            float theta;
            if (rho == 0.0f) theta = 0.0f;
            else {
                float r = __fdiv_rn(ccz, rho);
                r = fminf(1.0f, fmaxf(-1.0f, r));
                theta = __fdiv_rn(acosf(r), PI_F);
            }
            float f[10];
            f[0] = rho; f[1] = theta; f[2] = phi;
            f[3] = ux; f[4] = uy; f[5] = uz;
            f[6] = pos;
            f[7] = ccx; f[8] = ccy; f[9] = ccz;

            int chBase = t * 10;
#pragma unroll
            for (int c = 0; c < 10; c++) {
                float acc = 0.0f;
#pragma unroll
                for (int k = 0; k < 10; k++) acc += f[k] * sW1[c * 10 + k];
                float h = acc + sb1[c];
                d_h[(size_t)(chBase + c) * N_PTS + sp] = h;
                s0[c] += h;
                s1[c] += h * h;
            }

            if (bad) badm |= (1ULL << t);
            else if (first < 0) first = t;

            e1x = e2x; e1y = e2y; e1z = e2z;    // edge reuse
        }
    }

    // rare fix-up: replace bad triangles' normal/pos/cen features with first good's
    if (badm != 0ULL) {
        if (first < 0) first = 0;
        float fux, fuy, fuz, fcx, fcy, fcz, fpos;
        {
            int na = idxAt(first), nb = idxAt(nextT(first));
            float e1x, e1y, e1z, e2x, e2y, e2z;
            loadRel(na, e1x, e1y, e1z);
            loadRel(nb, e2x, e2y, e2z);
            float nx = __fsub_rn(__fmul_rn(e1y, e2z), __fmul_rn(e1z, e2y));
            float ny = __fsub_rn(__fmul_rn(e1z, e2x), __fmul_rn(e1x, e2z));
            float nz = __fsub_rn(__fmul_rn(e1x, e2y), __fmul_rn(e1y, e2x));
            float nl = __fsqrt_rn(sumsq_rn(nx, ny, nz));
            bool bad = (nl == 0.0f);
            if (bad) { fux = 0.0f; fuy = 0.0f; fuz = 0.0f; }
            else {
                fux = __fdiv_rn(nx, nl); fuy = __fdiv_rn(ny, nl); fuz = __fdiv_rn(nz, nl);
            }
            fux = __fmul_rn(fux, pm); fuy = __fmul_rn(fuy, pm); fuz = __fmul_rn(fuz, pm);
            fcx = __fdiv_rn(__fadd_rn(e1x, e2x), 3.0f);
            fcy = __fdiv_rn(__fadd_rn(e1y, e2y), 3.0f);
            fcz = __fdiv_rn(__fadd_rn(e1z, e2z), 3.0f);
            fpos = __fdiv_rn(
                __fadd_rn(__fadd_rn(__fmul_rn(fux, fcx), __fmul_rn(fuy, fcy)), __fmul_rn(fuz, fcz)),
                SQRT3_F);
        }
        unsigned long long m = badm;
        while (m) {
            int t = __ffsll((long long)m) - 1;
            m &= m - 1ULL;
            int na = idxAt(t), nb = idxAt(nextT(t));
            float e1x, e1y, e1z, e2x, e2y, e2z;
            loadRel(na, e1x, e1y, e1z);
            loadRel(nb, e2x, e2y, e2z);
            float ccx = __fdiv_rn(__fadd_rn(e1x, e2x), 3.0f);
            float ccy = __fdiv_rn(__fadd_rn(e1y, e2y), 3.0f);
            float ccz = __fdiv_rn(__fadd_rn(e1z, e2z), 3.0f);
            float rho = __fsqrt_rn(sumsq_rn(ccx, ccy, ccz));
            float phi = __fadd_rn(__fdiv_rn(atan2f(ccy, ccx), TWO_PI_F), 0.5f);
            float theta;
            if (rho == 0.0f) theta = 0.0f;
            else {
                float r = __fdiv_rn(ccz, rho);
                r = fminf(1.0f, fmaxf(-1.0f, r));
                theta = __fdiv_rn(acosf(r), PI_F);
            }
            float f[10];
            f[0] = rho; f[1] = theta; f[2] = phi;     // polar from OWN centroid
            f[3] = fux; f[4] = fuy; f[5] = fuz;       // replaced from first
            f[6] = fpos;
            f[7] = fcx; f[8] = fcy; f[9] = fcz;

            int chBase = t * 10;
#pragma unroll
            for (int c = 0; c < 10; c++) {
                float acc = 0.0f;
#pragma unroll
                for (int k = 0; k < 10; k++) acc += f[k] * sW1[c * 10 + k];
                float hn = acc + sb1[c];
                size_t off = (size_t)(chBase + c) * N_PTS + sp;
                float ho = d_h[off];
                d_h[off] = hn;
                s0[c] = s0[c] - ho + hn;
                s1[c] = s1[c] - ho * ho + hn * hn;
            }
        }
    }

    int lane = tid & 31, wrp = tid >> 5;
#pragma unroll
    for (int v = 0; v < 20; v++) {
        float a = (v < 10) ? s0[v] : s1[v - 10];
#pragma unroll
        for (int off = 16; off > 0; off >>= 1) a += __shfl_down_sync(0xFFFFFFFFu, a, off);
        if (lane == 0) sWS[wrp][v] = a;
    }
    __syncthreads();
    if (tid < 20) {
        float a = 0.0f;
#pragma unroll
        for (int w = 0; w < 8; w++) a += sWS[w][tid];
        d_part[blockIdx.x * 20 + tid] = a;
    }
}

// ---------------- BN finalize ----------------
__global__ __launch_bounds__(640) void bnK(const float* __restrict__ gamma,
                                           const float* __restrict__ beta) {
    __shared__ float S[20];
    int tid = threadIdx.x;
    int w = tid / 32, l = tid % 32;
    float a = 0.0f;
    for (int k = l; k < MBLK; k += 32) a += d_part[k * 20 + w];
#pragma unroll
    for (int off = 16; off > 0; off >>= 1) a += __shfl_down_sync(0xFFFFFFFFu, a, off);
    if (l == 0) S[w] = a;
    __syncthreads();
    if (tid < 10) {
        const double M = (double)N_PTS * 54.0;
        double mu = (double)S[tid] / M;
        double var = (double)S[tid + 10] / M - mu * mu;
        if (var < 0.0) var = 0.0;
        float sc = gamma[tid] * rsqrtf((float)var + 1e-5f);
        d_bn[tid] = sc;
        d_bn[10 + tid] = beta[tid] - (float)mu * sc;
    }
}

// ---------------- BN affine + relu + layer2 + sum over 54 (sorted order, scatter out) ----------------
__global__ __launch_bounds__(256) void outK(const float* __restrict__ W2,
                                            const float* __restrict__ b2,
                                            float* __restrict__ out) {
    __shared__ float sa[10], sb[10], sW2[100], sb2[10];
    int tid = threadIdx.x;
    if (tid < 10) { sa[tid] = d_bn[tid]; sb[tid] = d_bn[10 + tid]; sb2[tid] = b2[tid]; }
    if (tid < 100) sW2[tid] = W2[tid];
    __syncthreads();

    int sp = blockIdx.x * blockDim.x + tid;
    float acc[10];
#pragma unroll
    for (int c = 0; c < 10; c++) acc[c] = 0.0f;
    for (int t = 0; t < 54; t++) {
#pragma unroll
        for (int c = 0; c < 10; c++) {
            float v = d_h[(size_t)(t * 10 + c) * N_PTS + sp] * sa[c] + sb[c];
            v = fmaxf(v, 0.0f);
            acc[c] += v;
        }
    }
    int p = d_sid[sp];
#pragma unroll
    for (int c = 0; c < 10; c++) {
        float o = 54.0f * sb2[c];
#pragma unroll
        for (int j = 0; j < 10; j++) o += acc[j] * sW2[c * 10 + j];
        out[p * 10 + c] = o;
    }
}

// ---------------- launch ----------------
extern "C" void kernel_launch(void* const* d_in, const int* in_sizes, int n_in,
                              void* d_out, int out_size) {
    const float* center = (const float*)d_in[0];
    const float* W1 = (const float*)d_in[2];
    const float* b1 = (const float*)d_in[3];
    const float* gamma = (const float*)d_in[4];
    const float* beta = (const float*)d_in[5];
    const float* W2 = (const float*)d_in[6];
    const float* b2 = (const float*)d_in[7];
    float* out = (float*)d_out;

    void* cntPtr = nullptr;
    cudaGetSymbolAddress(&cntPtr, d_cnt);
    cudaMemsetAsync(cntPtr, 0, NCELL * sizeof(int), 0);

    countK<<<256, 256>>>(center);
    scanK<<<1, 1024>>>();
    scatterK<<<256, 256>>>(center);
    knnK<<<1024, 64>>>();
    sortK<<<8192, 256>>>(center);
    mlpK<<<MBLK, 256>>>(center, W1, b1);
    bnK<<<1, 640>>>(gamma, beta);
    outK<<<256, 256>>>(W2, b2, out);
}

// round 17
// speedup vs baseline: 1.4287x; 1.0407x over previous
#include <cuda_runtime.h>
#include <math_constants.h>

#define N_PTS 65536
#define KNNK 54
#define GRIDD 16
#define NCELL 4096
#define CELLH 0.0625f
#define MBLK 256     // mlpK: 256 blocks x 256 threads

#define TWO_PI_F 6.28318530717958647692f
#define PI_F     3.14159265358979323846f
#define SQRT3_F  1.73205080756887729353f

// ---------------- scratch (static device memory; no allocation) ----------------
__device__ float4 d_sorted[N_PTS];      // (x, y, z, psq) in grid-sorted order
__device__ int d_sid[N_PTS];            // original point id per sorted position
__device__ int d_cellStart[NCELL + 1];
__device__ int d_cellPtr[NCELL];
__device__ int d_cnt[NCELL];
__device__ unsigned long long d_key[N_PTS * KNNK];   // (mapped-d<<16)|orig_id, [sp][slot]
__device__ unsigned short d_idx16[N_PTS * KNNK];     // sorted neighbor orig-ids [sp][slot]
__device__ float d_h[N_PTS * KNNK * 10];             // [ch][sp]
__device__ float d_part[MBLK * 20];
__device__ float d_bn[20];

// canonical (+,+,+) octant: 27 cell offsets sorted by min box distance
__constant__ char4 c_ord[27] = {
    { 0, 0, 0, 0},
    { 1, 0, 0, 0}, { 0, 1, 0, 0}, { 0, 0, 1, 0},
    { 1, 1, 0, 0}, { 1, 0, 1, 0}, { 0, 1, 1, 0},
    { 1, 1, 1, 0},
    {-1, 0, 0, 0}, { 0,-1, 0, 0}, { 0, 0,-1, 0},
    {-1, 1, 0, 0}, {-1, 0, 1, 0}, { 1,-1, 0, 0},
    { 0,-1, 1, 0}, { 1, 0,-1, 0}, { 0, 1,-1, 0},
    {-1, 1, 1, 0}, { 1,-1, 1, 0}, { 1, 1,-1, 0},
    {-1,-1, 0, 0}, {-1, 0,-1, 0}, { 0,-1,-1, 0},
    {-1,-1, 1, 0}, {-1, 1,-1, 0}, { 1,-1,-1, 0},
    {-1,-1,-1, 0}
};

__device__ __forceinline__ int cellCoord(float v) {
    int c = (int)floorf(v * 16.0f);
    c = c < 0 ? 0 : c;
    return c > (GRIDD - 1) ? (GRIDD - 1) : c;
}

__device__ __forceinline__ float sumsq_rn(float x, float y, float z) {
    return __fadd_rn(__fadd_rn(__fmul_rn(x, x), __fmul_rn(y, y)), __fmul_rn(z, z));
}

__device__ __forceinline__ float dot3_fma(float ax, float ay, float az,
                                          float bx, float by, float bz) {
    return __fmaf_rn(az, bz, __fmaf_rn(ay, by, __fmul_rn(ax, bx)));
}

__device__ __forceinline__ unsigned mapf(float d) {
    unsigned u = __float_as_uint(d);
    return (u & 0x80000000u) ? ~u : (u | 0x80000000u);
}
__device__ __forceinline__ float unmapf(unsigned m) {
    unsigned u = (m & 0x80000000u) ? (m & 0x7FFFFFFFu) : ~m;
    return __uint_as_float(u);
}

// ---------------- grid build ----------------
__global__ void countK(const float* __restrict__ c) {
    int i = blockIdx.x * blockDim.x + threadIdx.x;
    if (i >= N_PTS) return;
    int cx = cellCoord(c[3 * i]);
    int cy = cellCoord(c[3 * i + 1]);
    int cz = cellCoord(c[3 * i + 2]);
    atomicAdd(&d_cnt[(cz * GRIDD + cy) * GRIDD + cx], 1);
}

__global__ __launch_bounds__(1024) void scanK() {
    __shared__ int s[1024];
    int t = threadIdx.x;
    int v0 = d_cnt[4 * t], v1 = d_cnt[4 * t + 1], v2 = d_cnt[4 * t + 2], v3 = d_cnt[4 * t + 3];
    int tot = v0 + v1 + v2 + v3;
    s[t] = tot;
    __syncthreads();
    for (int off = 1; off < 1024; off <<= 1) {
        int x = (t >= off) ? s[t - off] : 0;
        __syncthreads();
        s[t] += x;
        __syncthreads();
    }
    int excl = s[t] - tot;
    d_cellStart[4 * t] = excl;
    d_cellStart[4 * t + 1] = excl + v0;
    d_cellStart[4 * t + 2] = excl + v0 + v1;
    d_cellStart[4 * t + 3] = excl + v0 + v1 + v2;
    d_cellPtr[4 * t] = excl;
    d_cellPtr[4 * t + 1] = excl + v0;
    d_cellPtr[4 * t + 2] = excl + v0 + v1;
    d_cellPtr[4 * t + 3] = excl + v0 + v1 + v2;
    if (t == 1023) d_cellStart[NCELL] = s[1023];
}

__global__ void scatterK(const float* __restrict__ c) {
    int i = blockIdx.x * blockDim.x + threadIdx.x;
    if (i >= N_PTS) return;
    float x = c[3 * i], y = c[3 * i + 1], z = c[3 * i + 2];
    int cid = (cellCoord(z) * GRIDD + cellCoord(y)) * GRIDD + cellCoord(x);
    int pos = atomicAdd(&d_cellPtr[cid], 1);
    d_sorted[pos] = make_float4(x, y, z, sumsq_rn(x, y, z));
    d_sid[pos] = i;
}

// ---------------- KNN: u64 smem top-54, tracked worst group, 4-wide batch + id prefetch ----------------
__global__ __launch_bounds__(64) void knnK() {
    __shared__ unsigned long long sKV[KNNK * 64];
    int tid = threadIdx.x;
    int t = blockIdx.x * 64 + tid;      // sorted position
    float4 q = d_sorted[t];
    float qx = q.x, qy = q.y, qz = q.z;
    float qsq = q.w;
    int cx = cellCoord(qx), cy = cellCoord(qy), cz = cellCoord(qz);

    int count = 0;
    unsigned long long gm[9];
    unsigned long long wkey = 0xFFFFFFFFFFFFFFFFull;
    int wg = 0;
    float worst_d = CUDART_INF_F;

    auto accept = [&](float d, unsigned pi) {
        unsigned long long nk = ((unsigned long long)mapf(d) << 16) | pi;
        if (count < KNNK) {
            sKV[count * 64 + tid] = nk;
            count++;
            if (count == KNNK) {
                unsigned long long w = 0ULL; int wgl = 0;
#pragma unroll
                for (int g = 0; g < 9; g++) {
                    unsigned long long gv = 0ULL;
#pragma unroll
                    for (int j = 0; j < 6; j++) {
                        unsigned long long v = sKV[(g * 6 + j) * 64 + tid];
                        if (v > gv) gv = v;
                    }
                    gm[g] = gv;
                    if (gv > w) { w = gv; wgl = g; }
                }
                wkey = w; wg = wgl;
                worst_d = unmapf((unsigned)(w >> 16));
            }
        } else if (nk < wkey) {
            int base = wg * 6;
            unsigned long long m1 = 0ULL, m2 = 0ULL;
            int ms = base;
#pragma unroll
            for (int j = 0; j < 6; j++) {
                unsigned long long v = sKV[(base + j) * 64 + tid];
                if (v > m1) { m2 = m1; m1 = v; ms = base + j; }
                else if (v > m2) m2 = v;
            }
            sKV[ms * 64 + tid] = nk;
            gm[wg] = nk > m2 ? nk : m2;
            unsigned long long w = gm[0]; int wgl = 0;
#pragma unroll
            for (int g = 1; g < 9; g++) if (gm[g] > w) { w = gm[g]; wgl = g; }
            wkey = w; wg = wgl;
            worst_d = unmapf((unsigned)(w >> 16));
        }
    };

    auto processCell = [&](int cid) {
        int s = d_cellStart[cid], e = d_cellStart[cid + 1];
        int p = s;
        for (; p + 4 <= e; p += 4) {
            float4 a0 = d_sorted[p];
            float4 a1 = d_sorted[p + 1];
            float4 a2 = d_sorted[p + 2];
            float4 a3 = d_sorted[p + 3];
            unsigned i0 = (unsigned)d_sid[p];        // independent prefetch:
            unsigned i1 = (unsigned)d_sid[p + 1];    // removes dependent load from
            unsigned i2 = (unsigned)d_sid[p + 2];    // the accept path
            unsigned i3 = (unsigned)d_sid[p + 3];
            float d0 = __fsub_rn(__fadd_rn(qsq, a0.w),
                                 __fmul_rn(2.0f, dot3_fma(qx, qy, qz, a0.x, a0.y, a0.z)));
            float d1 = __fsub_rn(__fadd_rn(qsq, a1.w),
                                 __fmul_rn(2.0f, dot3_fma(qx, qy, qz, a1.x, a1.y, a1.z)));
            float d2 = __fsub_rn(__fadd_rn(qsq, a2.w),
                                 __fmul_rn(2.0f, dot3_fma(qx, qy, qz, a2.x, a2.y, a2.z)));
            float d3 = __fsub_rn(__fadd_rn(qsq, a3.w),
                                 __fmul_rn(2.0f, dot3_fma(qx, qy, qz, a3.x, a3.y, a3.z)));
            if (d0 <= worst_d) accept(d0, i0);
            if (d1 <= worst_d) accept(d1, i1);
            if (d2 <= worst_d) accept(d2, i2);
            if (d3 <= worst_d) accept(d3, i3);
        }
        for (; p < e; p++) {
            float4 a = d_sorted[p];
            unsigned pi = (unsigned)d_sid[p];
            float d = __fsub_rn(__fadd_rn(qsq, a.w),
                                __fmul_rn(2.0f, dot3_fma(qx, qy, qz, a.x, a.y, a.z)));
            if (d <= worst_d) accept(d, pi);
        }
    };

    int sx = (qx > ((float)cx + 0.5f) * CELLH) ? 1 : -1;
    int sy = (qy > ((float)cy + 0.5f) * CELLH) ? 1 : -1;
    int sz = (qz > ((float)cz + 0.5f) * CELLH) ? 1 : -1;

#pragma unroll 1
    for (int o = 0; o < 27; o++) {
        char4 c = c_ord[o];
        int x = cx + sx * (int)c.x;
        int y = cy + sy * (int)c.y;
        int z = cz + sz * (int)c.z;
        if (((unsigned)x | (unsigned)y | (unsigned)z) > 15u) continue;
        float dxx = fmaxf(0.0f, fmaxf((float)x * CELLH - qx, qx - ((float)x * CELLH + CELLH)));
        float dyy = fmaxf(0.0f, fmaxf((float)y * CELLH - qy, qy - ((float)y * CELLH + CELLH)));
        float dzz = fmaxf(0.0f, fmaxf((float)z * CELLH - qz, qz - ((float)z * CELLH + CELLH)));
        if (dxx * dxx + dyy * dyy + dzz * dzz > worst_d + 4e-6f) continue;
        processCell((z * GRIDD + y) * GRIDD + x);
    }

    {
        float g = CUDART_INF_F;
        if (cx - 1 > 0)         g = fminf(g, qx - (float)(cx - 1) * CELLH);
        if (cx + 1 < GRIDD - 1) g = fminf(g, (float)(cx + 2) * CELLH - qx);
        if (cy - 1 > 0)         g = fminf(g, qy - (float)(cy - 1) * CELLH);
        if (cy + 1 < GRIDD - 1) g = fminf(g, (float)(cy + 2) * CELLH - qy);
        if (cz - 1 > 0)         g = fminf(g, qz - (float)(cz - 1) * CELLH);
        if (cz + 1 < GRIDD - 1) g = fminf(g, (float)(cz + 2) * CELLH - qz);
        if (worst_d + 4e-6f < g * g) goto done;
    }

    {
        int maxm = cx; if (GRIDD - 1 - cx > maxm) maxm = GRIDD - 1 - cx;
        if (cy > maxm) maxm = cy; if (GRIDD - 1 - cy > maxm) maxm = GRIDD - 1 - cy;
        if (cz > maxm) maxm = cz; if (GRIDD - 1 - cz > maxm) maxm = GRIDD - 1 - cz;

        for (int m = 2; m <= maxm; m++) {
            int zlo = cz - m < 0 ? 0 : cz - m;
            int zhi = cz + m > GRIDD - 1 ? GRIDD - 1 : cz + m;
            for (int z = zlo; z <= zhi; z++) {
                int adz = z - cz; adz = adz < 0 ? -adz : adz;
                float lo = (float)z * CELLH, hi = lo + CELLH;
                float dz = fmaxf(0.0f, fmaxf(lo - qz, qz - hi));
                float dz2 = dz * dz;
                int ylo = cy - m < 0 ? 0 : cy - m;
                int yhi = cy + m > GRIDD - 1 ? GRIDD - 1 : cy + m;
                for (int y = ylo; y <= yhi; y++) {
                    int ady = y - cy; ady = ady < 0 ? -ady : ady;
                    float lyo = (float)y * CELLH, lyh = lyo + CELLH;
                    float dy = fmaxf(0.0f, fmaxf(lyo - qy, qy - lyh));
                    float dyz2 = dz2 + dy * dy;
                    if (dyz2 > worst_d + 4e-6f) continue;
                    int xlo = cx - m < 0 ? 0 : cx - m;
                    int xhi = cx + m > GRIDD - 1 ? GRIDD - 1 : cx + m;
                    for (int x = xlo; x <= xhi; x++) {
                        int adx = x - cx; adx = adx < 0 ? -adx : adx;
                        int cheb = adx > ady ? adx : ady;
                        if (adz > cheb) cheb = adz;
                        if (cheb != m) continue;
                        float lxo = (float)x * CELLH, lxh = lxo + CELLH;
                        float dx = fmaxf(0.0f, fmaxf(lxo - qx, qx - lxh));
                        if (dyz2 + dx * dx > worst_d + 4e-6f) continue;
                        processCell((z * GRIDD + y) * GRIDD + x);
                    }
                }
            }
            float g = CUDART_INF_F;
            if (cx - m > 0)         g = fminf(g, qx - (float)(cx - m) * CELLH);
            if (cx + m < GRIDD - 1) g = fminf(g, (float)(cx + m + 1) * CELLH - qx);
            if (cy - m > 0)         g = fminf(g, qy - (float)(cy - m) * CELLH);
            if (cy + m < GRIDD - 1) g = fminf(g, (float)(cy + m + 1) * CELLH - qy);
            if (cz - m > 0)         g = fminf(g, qz - (float)(cz - m) * CELLH);
            if (cz + m < GRIDD - 1) g = fminf(g, (float)(cz + m + 1) * CELLH - qz);
            if (worst_d + 4e-6f < g * g) break;
        }
    }

done:
#pragma unroll
    for (int j = 0; j < KNNK; j++) d_key[(size_t)t * KNNK + j] = sKV[j * 64 + tid];
}

// ---------------- sortK: warp-per-point register bitonic sorts (R13 version) ----------------
__device__ __forceinline__ void ceA(unsigned long long& h, unsigned& l, int dl, bool keep_min) {
    unsigned long long oh = __shfl_xor_sync(0xFFFFFFFFu, h, dl);
    unsigned ol = __shfl_xor_sync(0xFFFFFFFFu, l, dl);
    bool mine_le = (h < oh) || (h == oh && l <= ol);
    if (mine_le != keep_min) { h = oh; l = ol; }
}
__device__ __forceinline__ void ceB(unsigned long long& h, int dl, bool keep_min) {
    unsigned long long oh = __shfl_xor_sync(0xFFFFFFFFu, h, dl);
    bool mine_le = (h <= oh);
    if (mine_le != keep_min) h = oh;
}

__global__ __launch_bounds__(256) void sortK(const float* __restrict__ cen) {
    int tid = threadIdx.x;
    int lane = tid & 31;
    int wrp = tid >> 5;
    int sp = blockIdx.x * 8 + wrp;

    float4 q = d_sorted[sp];
    float qx = q.x, qy = q.y, qz = q.z;

    const int e0 = 2 * lane, e1 = 2 * lane + 1;
    unsigned long long h0 = ~0ULL, h1 = ~0ULL;
    unsigned l0 = 0xFFFFFFFFu, l1 = 0xFFFFFFFFu;

#pragma unroll
    for (int s = 0; s < 2; s++) {
        int e = s ? e1 : e0;
        if (e < KNNK) {
            unsigned long long k = d_key[(size_t)sp * KNNK + e];
            unsigned id = (unsigned)(k & 0xFFFFull);
            unsigned d32 = (unsigned)(k >> 16);
            float x = __fsub_rn(cen[3 * id], qx);
            float y = __fsub_rn(cen[3 * id + 1], qy);
            float z = __fsub_rn(cen[3 * id + 2], qz);
            float rx = __fmaf_rn(z, -0.5f,    __fmaf_rn(y, 0.7071f, __fmul_rn(x,  0.5f)));
            float ry = __fmaf_rn(z,  0.5f,    __fmaf_rn(y, 0.7071f, __fmul_rn(x, -0.5f)));
            float rz = __fmaf_rn(z,  0.7071f, __fmul_rn(x, 0.7071f));
            float rho = __fsqrt_rn(sumsq_rn(rx, ry, rz));
            unsigned long long h = ((unsigned long long)mapf(rho) << 32) | (unsigned long long)d32;
            if (s) { h1 = h; l1 = id; } else { h0 = h; l0 = id; }
        }
    }

#pragma unroll
    for (int k = 2; k <= 64; k <<= 1) {
        bool asc = ((lane & (k >> 1)) == 0);
#pragma unroll
        for (int j = k >> 1; j >= 2; j >>= 1) {
            int dl = j >> 1;
            bool km = (((lane & dl) == 0) == asc);
            ceA(h0, l0, dl, km);
            ceA(h1, l1, dl, km);
        }
        bool r0_le = (h0 < h1) || (h0 == h1 && l0 <= l1);
        if (r0_le != asc) {
            unsigned long long th = h0; h0 = h1; h1 = th;
            unsigned tl = l0; l0 = l1; l1 = tl;
        }
    }

    unsigned long long b0 = ~0ULL, b1 = ~0ULL;
#pragma unroll
    for (int s = 0; s < 2; s++) {
        int e = s ? e1 : e0;
        unsigned id = (s ? l1 : l0) & 0xFFFFu;
        if (e < KNNK) {
            float x = __fsub_rn(cen[3 * id], qx);
            float y = __fsub_rn(cen[3 * id + 1], qy);
            float z = __fsub_rn(cen[3 * id + 2], qz);
            float rx = __fmaf_rn(z, -0.5f, __fmaf_rn(y, 0.7071f, __fmul_rn(x,  0.5f)));
            float ry = __fmaf_rn(z,  0.5f, __fmaf_rn(y, 0.7071f, __fmul_rn(x, -0.5f)));
            float phi = __fadd_rn(__fdiv_rn(atan2f(ry, rx), TWO_PI_F), 0.5f);
            unsigned long long seg = (e < 9) ? 0ULL : (e < 27) ? 1ULL : 2ULL;
            unsigned long long b = (seg << 54)
                                 | ((unsigned long long)mapf(phi) << 22)
                                 | ((unsigned long long)e << 16)
                                 | (unsigned long long)id;
            if (s) b1 = b; else b0 = b;
        }
    }

#pragma unroll
    for (int k = 2; k <= 64; k <<= 1) {
        bool asc = ((lane & (k >> 1)) == 0);
#pragma unroll
        for (int j = k >> 1; j >= 2; j >>= 1) {
            int dl = j >> 1;
            bool km = (((lane & dl) == 0) == asc);
            ceB(b0, dl, km);
            ceB(b1, dl, km);
        }
        if ((b0 <= b1) != asc) {
            unsigned long long tb = b0; b0 = b1; b1 = tb;
        }
    }

    if (e0 < KNNK) d_idx16[(size_t)sp * KNNK + e0] = (unsigned short)(b0 & 0xFFFFull);
    if (e1 < KNNK) d_idx16[(size_t)sp * KNNK + e1] = (unsigned short)(b1 & 0xFFFFull);
}

// ---------------- mlpK: single pass, edge reuse (1 new gather per triangle), rare fixup ----------------
__global__ __launch_bounds__(256) void mlpK(const float* __restrict__ cen,
                                            const float* __restrict__ W1,
                                            const float* __restrict__ b1) {
    __shared__ float sW1[100], sb1[10];
    __shared__ float sWS[8][20];
    int tid = threadIdx.x;
    if (tid < 100) sW1[tid] = W1[tid];
    if (tid < 10) sb1[tid] = b1[tid];
    __syncthreads();

    int sp = blockIdx.x * 256 + tid;
    float4 q = d_sorted[sp];
    float qx = q.x, qy = q.y, qz = q.z;

    auto idxAt = [&](int i) -> int { return (int)d_idx16[(size_t)sp * KNNK + i]; };
    auto nextT = [](int t) -> int {
        int base, len;
        if (t < 9) { base = 0; len = 9; }
        else if (t < 27) { base = 9; len = 18; }
        else { base = 27; len = 27; }
        int loc = t - base + 1;
        return base + (loc == len ? 0 : loc);
    };
    auto loadRel = [&](int id, float& ex, float& ey, float& ez) {
        ex = __fsub_rn(cen[3 * id], qx);
        ey = __fsub_rn(cen[3 * id + 1], qy);
        ez = __fsub_rn(cen[3 * id + 2], qz);
    };

    float pm = 1.0f;
    unsigned long long badm = 0ULL;
    int first = -1;

    float s0[10], s1[10];
#pragma unroll
    for (int c = 0; c < 10; c++) { s0[c] = 0.0f; s1[c] = 0.0f; }

    // single pass over 3 segments; e2(t) == e1(t+1) within a segment
    for (int seg = 0; seg < 3; seg++) {
        int base = (seg == 0) ? 0 : (seg == 1) ? 9 : 27;
        int len  = (seg == 0) ? 9 : (seg == 1) ? 18 : 27;
        float fx, fy, fz;                       // segment-first edge (for wrap)
        loadRel(idxAt(base), fx, fy, fz);
        float e1x = fx, e1y = fy, e1z = fz;
        for (int loc = 0; loc < len; loc++) {
            int t = base + loc;
            float e2x, e2y, e2z;
            if (loc == len - 1) { e2x = fx; e2y = fy; e2z = fz; }
            else loadRel(idxAt(t + 1), e2x, e2y, e2z);

            float nx = __fsub_rn(__fmul_rn(e1y, e2z), __fmul_rn(e1z, e2y));
            float ny = __fsub_rn(__fmul_rn(e1z, e2x), __fmul_rn(e1x, e2z));
            float nz = __fsub_rn(__fmul_rn(e1x, e2y), __fmul_rn(e1y, e2x));
            float nl = __fsqrt_rn(sumsq_rn(nx, ny, nz));
            bool bad = (nl == 0.0f);
            float ux, uy, uz;
            if (bad) { ux = 0.0f; uy = 0.0f; uz = 0.0f; }
            else {
                ux = __fdiv_rn(nx, nl); uy = __fdiv_rn(ny, nl); uz = __fdiv_rn(nz, nl);
            }
            if (t == 0) pm = (ux > 0.0f) ? 1.0f : -1.0f;
            ux = __fmul_rn(ux, pm); uy = __fmul_rn(uy, pm); uz = __fmul_rn(uz, pm);
            float ccx = __fdiv_rn(__fadd_rn(e1x, e2x), 3.0f);
            float ccy = __fdiv_rn(__fadd_rn(e1y, e2y), 3.0f);
            float ccz = __fdiv_rn(__fadd_rn(e1z, e2z), 3.0f);
            float pos = __fdiv_rn(
                __fadd_rn(__fadd_rn(__fmul_rn(ux, ccx), __fmul_rn(uy, ccy)), __fmul_rn(uz, ccz)),
                SQRT3_F);

            float rho = __fsqrt_rn(sumsq_rn(ccx, ccy, ccz));
            float phi = __fadd_rn(__fdiv_rn(atan2f(ccy, ccx), TWO_PI_F), 0.5f);
            float theta;
            if (rho == 0.0f) theta = 0.0f;
            else {
                float r = __fdiv_rn(ccz, rho);
                r = fminf(1.0f, fmaxf(-1.0f, r));
                theta = __fdiv_rn(acosf(r), PI_F);
            }
            float f[10];
            f[0] = rho; f[1] = theta; f[2] = phi;
            f[3] = ux; f[4] = uy; f[5] = uz;
            f[6] = pos;
            f[7] = ccx; f[8] = ccy; f[9] = ccz;

            int chBase = t * 10;
#pragma unroll
            for (int c = 0; c < 10; c++) {
                float acc = 0.0f;
#pragma unroll
                for (int k = 0; k < 10; k++) acc += f[k] * sW1[c * 10 + k];
                float h = acc + sb1[c];
                d_h[(size_t)(chBase + c) * N_PTS + sp] = h;
                s0[c] += h;
                s1[c] += h * h;
            }

            if (bad) badm |= (1ULL << t);
            else if (first < 0) first = t;

            e1x = e2x; e1y = e2y; e1z = e2z;    // edge reuse
        }
    }

    // rare fix-up: replace bad triangles' normal/pos/cen features with first good's
    if (badm != 0ULL) {
        if (first < 0) first = 0;
        float fux, fuy, fuz, fcx, fcy, fcz, fpos;
        {
            int na = idxAt(first), nb = idxAt(nextT(first));
            float e1x, e1y, e1z, e2x, e2y, e2z;
            loadRel(na, e1x, e1y, e1z);
            loadRel(nb, e2x, e2y, e2z);
            float nx = __fsub_rn(__fmul_rn(e1y, e2z), __fmul_rn(e1z, e2y));
            float ny = __fsub_rn(__fmul_rn(e1z, e2x), __fmul_rn(e1x, e2z));
            float nz = __fsub_rn(__fmul_rn(e1x, e2y), __fmul_rn(e1y, e2x));
            float nl = __fsqrt_rn(sumsq_rn(nx, ny, nz));
            bool bad = (nl == 0.0f);
            if (bad) { fux = 0.0f; fuy = 0.0f; fuz = 0.0f; }
            else {
                fux = __fdiv_rn(nx, nl); fuy = __fdiv_rn(ny, nl); fuz = __fdiv_rn(nz, nl);
            }
            fux = __fmul_rn(fux, pm); fuy = __fmul_rn(fuy, pm); fuz = __fmul_rn(fuz, pm);
            fcx = __fdiv_rn(__fadd_rn(e1x, e2x), 3.0f);
            fcy = __fdiv_rn(__fadd_rn(e1y, e2y), 3.0f);
            fcz = __fdiv_rn(__fadd_rn(e1z, e2z), 3.0f);
            fpos = __fdiv_rn(
                __fadd_rn(__fadd_rn(__fmul_rn(fux, fcx), __fmul_rn(fuy, fcy)), __fmul_rn(fuz, fcz)),
                SQRT3_F);
        }
        unsigned long long m = badm;
        while (m) {
            int t = __ffsll((long long)m) - 1;
            m &= m - 1ULL;
            int na = idxAt(t), nb = idxAt(nextT(t));
            float e1x, e1y, e1z, e2x, e2y, e2z;
            loadRel(na, e1x, e1y, e1z);
            loadRel(nb, e2x, e2y, e2z);
            float ccx = __fdiv_rn(__fadd_rn(e1x, e2x), 3.0f);
            float ccy = __fdiv_rn(__fadd_rn(e1y, e2y), 3.0f);
            float ccz = __fdiv_rn(__fadd_rn(e1z, e2z), 3.0f);
            float rho = __fsqrt_rn(sumsq_rn(ccx, ccy, ccz));
            float phi = __fadd_rn(__fdiv_rn(atan2f(ccy, ccx), TWO_PI_F), 0.5f);
            float theta;
            if (rho == 0.0f) theta = 0.0f;
            else {
                float r = __fdiv_rn(ccz, rho);
                r = fminf(1.0f, fmaxf(-1.0f, r));
                theta = __fdiv_rn(acosf(r), PI_F);
            }
            float f[10];
            f[0] = rho; f[1] = theta; f[2] = phi;     // polar from OWN centroid
            f[3] = fux; f[4] = fuy; f[5] = fuz;       // replaced from first
            f[6] = fpos;
            f[7] = fcx; f[8] = fcy; f[9] = fcz;

            int chBase = t * 10;
#pragma unroll
            for (int c = 0; c < 10; c++) {
                float acc = 0.0f;
#pragma unroll
                for (int k = 0; k < 10; k++) acc += f[k] * sW1[c * 10 + k];
                float hn = acc + sb1[c];
                size_t off = (size_t)(chBase + c) * N_PTS + sp;
                float ho = d_h[off];
                d_h[off] = hn;
                s0[c] = s0[c] - ho + hn;
                s1[c] = s1[c] - ho * ho + hn * hn;
            }
        }
    }

    int lane = tid & 31, wrp = tid >> 5;
#pragma unroll
    for (int v = 0; v < 20; v++) {
        float a = (v < 10) ? s0[v] : s1[v - 10];
#pragma unroll
        for (int off = 16; off > 0; off >>= 1) a += __shfl_down_sync(0xFFFFFFFFu, a, off);
        if (lane == 0) sWS[wrp][v] = a;
    }
    __syncthreads();
    if (tid < 20) {
        float a = 0.0f;
#pragma unroll
        for (int w = 0; w < 8; w++) a += sWS[w][tid];
        d_part[blockIdx.x * 20 + tid] = a;
    }
}

// ---------------- BN finalize ----------------
__global__ __launch_bounds__(640) void bnK(const float* __restrict__ gamma,
                                           const float* __restrict__ beta) {
    __shared__ float S[20];
    int tid = threadIdx.x;
    int w = tid / 32, l = tid % 32;
    float a = 0.0f;
    for (int k = l; k < MBLK; k += 32) a += d_part[k * 20 + w];
#pragma unroll
    for (int off = 16; off > 0; off >>= 1) a += __shfl_down_sync(0xFFFFFFFFu, a, off);
    if (l == 0) S[w] = a;
    __syncthreads();
    if (tid < 10) {
        const double M = (double)N_PTS * 54.0;
        double mu = (double)S[tid] / M;
        double var = (double)S[tid + 10] / M - mu * mu;
        if (var < 0.0) var = 0.0;
        float sc = gamma[tid] * rsqrtf((float)var + 1e-5f);
        d_bn[tid] = sc;
        d_bn[10 + tid] = beta[tid] - (float)mu * sc;
    }
}

// ---------------- BN affine + relu + layer2 + sum over 54 (sorted order, scatter out) ----------------
__global__ __launch_bounds__(256) void outK(const float* __restrict__ W2,
                                            const float* __restrict__ b2,
                                            float* __restrict__ out) {
    __shared__ float sa[10], sb[10], sW2[100], sb2[10];
    int tid = threadIdx.x;
    if (tid < 10) { sa[tid] = d_bn[tid]; sb[tid] = d_bn[10 + tid]; sb2[tid] = b2[tid]; }
    if (tid < 100) sW2[tid] = W2[tid];
    __syncthreads();

    int sp = blockIdx.x * blockDim.x + tid;
    float acc[10];
#pragma unroll
    for (int c = 0; c < 10; c++) acc[c] = 0.0f;
    for (int t = 0; t < 54; t++) {
#pragma unroll
        for (int c = 0; c < 10; c++) {
            float v = d_h[(size_t)(t * 10 + c) * N_PTS + sp] * sa[c] + sb[c];
            v = fmaxf(v, 0.0f);
            acc[c] += v;
        }
    }
    int p = d_sid[sp];
#pragma unroll
    for (int c = 0; c < 10; c++) {
        float o = 54.0f * sb2[c];
#pragma unroll
        for (int j = 0; j < 10; j++) o += acc[j] * sW2[c * 10 + j];
        out[p * 10 + c] = o;
    }
}

// ---------------- launch ----------------
extern "C" void kernel_launch(void* const* d_in, const int* in_sizes, int n_in,
                              void* d_out, int out_size) {
    const float* center = (const float*)d_in[0];
    const float* W1 = (const float*)d_in[2];
    const float* b1 = (const float*)d_in[3];
    const float* gamma = (const float*)d_in[4];
    const float* beta = (const float*)d_in[5];
    const float* W2 = (const float*)d_in[6];
    const float* b2 = (const float*)d_in[7];
    float* out = (float*)d_out;

    void* cntPtr = nullptr;
    cudaGetSymbolAddress(&cntPtr, d_cnt);
    cudaMemsetAsync(cntPtr, 0, NCELL * sizeof(int), 0);

    countK<<<256, 256>>>(center);
    scanK<<<1, 1024>>>();
    scatterK<<<256, 256>>>(center);
    knnK<<<1024, 64>>>();
    sortK<<<8192, 256>>>(center);
    mlpK<<<MBLK, 256>>>(center, W1, b1);
    bnK<<<1, 640>>>(gamma, beta);
    outK<<<256, 256>>>(W2, b2, out);
}